// round 2
// baseline (speedup 1.0000x reference)
#include <cuda_runtime.h>
#include <math.h>

// Problem dims
#define Bz  8
#define Tz  1024
#define Cz  1024
#define Hz  16
#define Dz  64
#define TIz 256
#define FFz 4096

// ---------------- scratch (device globals; no allocation allowed) ----------
__device__ float g_h   [Bz * Tz * Cz];        // LN output (reused 3x)
__device__ float g_qkv [Bz * Tz * 3 * Cz];    // fused qkv
__device__ float g_attn[Bz * Tz * Cz];        // merged attention output (reused 2x)
__device__ float g_x   [Bz * Tz * Cz];        // running residual
__device__ float g_q2  [Bz * Tz * Cz];        // cross-attn q
__device__ float g_k2  [Bz * TIz * Cz];       // cross-attn k
__device__ float g_v2  [Bz * TIz * Cz];       // cross-attn v
__device__ float g_ff  [Bz * Tz * FFz];       // MLP hidden

// ---------------- LayerNorm: one row (C=1024) per block of 256 threads -----
__global__ void ln_kernel(const float* __restrict__ x,
                          const float* __restrict__ gam,
                          const float* __restrict__ bet,
                          float* __restrict__ out) {
    int row = blockIdx.x;
    const float4* xp = (const float4*)(x + (size_t)row * Cz);
    float4 v = xp[threadIdx.x];
    float s  = v.x + v.y + v.z + v.w;
    float sq = v.x * v.x + v.y * v.y + v.z * v.z + v.w * v.w;

    __shared__ float rs[8], rq[8];
    #pragma unroll
    for (int o = 16; o > 0; o >>= 1) {
        s  += __shfl_down_sync(0xffffffffu, s,  o);
        sq += __shfl_down_sync(0xffffffffu, sq, o);
    }
    int wid = threadIdx.x >> 5, lid = threadIdx.x & 31;
    if (lid == 0) { rs[wid] = s; rq[wid] = sq; }
    __syncthreads();
    if (wid == 0) {
        s  = (lid < 8) ? rs[lid] : 0.f;
        sq = (lid < 8) ? rq[lid] : 0.f;
        #pragma unroll
        for (int o = 4; o > 0; o >>= 1) {
            s  += __shfl_down_sync(0xffffffffu, s,  o);
            sq += __shfl_down_sync(0xffffffffu, sq, o);
        }
        if (lid == 0) { rs[0] = s; rq[0] = sq; }
    }
    __syncthreads();
    float mu  = rs[0] * (1.0f / Cz);
    float var = rq[0] * (1.0f / Cz) - mu * mu;
    float inv = rsqrtf(var + 1e-5f);

    float4 gv = ((const float4*)gam)[threadIdx.x];
    float4 bv = ((const float4*)bet)[threadIdx.x];
    float4 o4;
    o4.x = (v.x - mu) * inv * gv.x + bv.x;
    o4.y = (v.y - mu) * inv * gv.y + bv.y;
    o4.z = (v.z - mu) * inv * gv.z + bv.z;
    o4.w = (v.w - mu) * inv * gv.w + bv.w;
    ((float4*)(out + (size_t)row * Cz))[threadIdx.x] = o4;
}

// ---------------- SGEMM 128x128x8, 256 threads, 8x8 per thread -------------
__device__ __forceinline__ float gelu_tanh(float v) {
    float t = tanhf(0.7978845608028654f * (v + 0.044715f * v * v * v));
    return 0.5f * v * (1.0f + t);
}

#define BM 128
#define BN 128
#define BK 8

__global__ __launch_bounds__(256)
void sgemm(const float* __restrict__ A, const float* __restrict__ Bm,
           const float* __restrict__ bias, const float* __restrict__ Res,
           float* __restrict__ Cm, int M, int N, int K, int act) {
    __shared__ __align__(16) float As[BK][BM];
    __shared__ __align__(16) float Bs[BK][BN];

    int tid = threadIdx.x;
    int bm = blockIdx.y * BM, bn = blockIdx.x * BN;

    int arow = tid >> 1, acol = (tid & 1) * 4;      // A: 128 rows x 8 cols as float4
    int brow = tid >> 5, bcol = (tid & 31) * 4;     // B: 8 rows x 128 cols as float4
    int tx = tid & 15, ty = tid >> 4;

    float acc[8][8];
    #pragma unroll
    for (int i = 0; i < 8; i++)
        #pragma unroll
        for (int j = 0; j < 8; j++) acc[i][j] = 0.f;

    const float* Aptr = A + (size_t)(bm + arow) * K + acol;
    const float* Bptr = Bm + (size_t)brow * N + bn + bcol;

    for (int k0 = 0; k0 < K; k0 += BK) {
        float4 a4 = *(const float4*)(Aptr + k0);
        float4 b4 = *(const float4*)(Bptr + (size_t)k0 * N);
        As[acol + 0][arow] = a4.x;
        As[acol + 1][arow] = a4.y;
        As[acol + 2][arow] = a4.z;
        As[acol + 3][arow] = a4.w;
        *(float4*)&Bs[brow][bcol] = b4;
        __syncthreads();

        #pragma unroll
        for (int kk = 0; kk < BK; kk++) {
            float4 a0 = *(const float4*)&As[kk][ty * 8];
            float4 a1 = *(const float4*)&As[kk][ty * 8 + 4];
            float4 b0 = *(const float4*)&Bs[kk][tx * 8];
            float4 b1 = *(const float4*)&Bs[kk][tx * 8 + 4];
            float ra[8] = {a0.x, a0.y, a0.z, a0.w, a1.x, a1.y, a1.z, a1.w};
            float rb[8] = {b0.x, b0.y, b0.z, b0.w, b1.x, b1.y, b1.z, b1.w};
            #pragma unroll
            for (int i = 0; i < 8; i++)
                #pragma unroll
                for (int j = 0; j < 8; j++)
                    acc[i][j] += ra[i] * rb[j];
        }
        __syncthreads();
    }

    float bias0[8];
    #pragma unroll
    for (int j = 0; j < 8; j++) bias0[j] = bias[bn + tx * 8 + j];

    #pragma unroll
    for (int i = 0; i < 8; i++) {
        size_t off = (size_t)(bm + ty * 8 + i) * N + bn + tx * 8;
        float c[8];
        #pragma unroll
        for (int j = 0; j < 8; j++) c[j] = acc[i][j] + bias0[j];
        if (Res) {
            float4 r0 = *(const float4*)(Res + off);
            float4 r1 = *(const float4*)(Res + off + 4);
            c[0] += r0.x; c[1] += r0.y; c[2] += r0.z; c[3] += r0.w;
            c[4] += r1.x; c[5] += r1.y; c[6] += r1.z; c[7] += r1.w;
        }
        if (act) {
            #pragma unroll
            for (int j = 0; j < 8; j++) c[j] = gelu_tanh(c[j]);
        }
        float4 o0 = make_float4(c[0], c[1], c[2], c[3]);
        float4 o1 = make_float4(c[4], c[5], c[6], c[7]);
        *(float4*)(Cm + off) = o0;
        *(float4*)(Cm + off + 4) = o1;
    }
}

// ---------------- Flash attention: 1 query row per thread ------------------
// Block: 128 threads = 128 query rows. K/V staged in smem (64-key tiles),
// read as broadcast float4 LDS. Online softmax with rare rescale.
template <bool CAUSAL>
__global__ __launch_bounds__(128)
void attn_kernel(const float* __restrict__ Q, int qld,
                 const float* __restrict__ K, int kld,
                 const float* __restrict__ V, int vld,
                 float* __restrict__ O, int oldd,
                 int Tq, int S) {
    __shared__ float4 Ks[64 * 16];
    __shared__ float4 Vs[64 * 16];

    int bh = blockIdx.y;
    int b = bh >> 4, h = bh & 15;
    const float* qb = Q + (size_t)b * Tq * qld + h * Dz;
    const float* kb = K + (size_t)b * S * kld + h * Dz;
    const float* vb = V + (size_t)b * S * vld + h * Dz;
    float* ob = O + (size_t)b * Tq * oldd + h * Dz;

    int t = blockIdx.x * 128 + threadIdx.x;

    float4 q4[16], a4[16];
    const float4* qp = (const float4*)(qb + (size_t)t * qld);
    #pragma unroll
    for (int j = 0; j < 16; j++) {
        q4[j] = qp[j];
        a4[j] = make_float4(0.f, 0.f, 0.f, 0.f);
    }
    float m = -1e30f, l = 0.f;

    int smax = CAUSAL ? (blockIdx.x * 128 + 128) : S;
    for (int s0 = 0; s0 < smax; s0 += 64) {
        __syncthreads();
        for (int i = threadIdx.x; i < 64 * 16; i += 128) {
            int r = i >> 4, c = i & 15;
            Ks[i] = ((const float4*)(kb + (size_t)(s0 + r) * kld))[c];
            Vs[i] = ((const float4*)(vb + (size_t)(s0 + r) * vld))[c];
        }
        __syncthreads();
        int send = min(64, smax - s0);
        for (int s = 0; s < send; s++) {
            bool active = !(CAUSAL && (s0 + s) > t);
            if (active) {
                float dot = 0.f;
                #pragma unroll
                for (int j = 0; j < 16; j++) {
                    float4 kk = Ks[(s << 4) + j];
                    dot += q4[j].x * kk.x + q4[j].y * kk.y +
                           q4[j].z * kk.z + q4[j].w * kk.w;
                }
                dot *= 0.125f;  // 1/sqrt(64)
                float mn = fmaxf(m, dot);
                float p = __expf(dot - mn);
                if (mn > m) {
                    float sc = __expf(m - mn);
                    l *= sc;
                    #pragma unroll
                    for (int j = 0; j < 16; j++) {
                        a4[j].x *= sc; a4[j].y *= sc;
                        a4[j].z *= sc; a4[j].w *= sc;
                    }
                    m = mn;
                }
                l += p;
                #pragma unroll
                for (int j = 0; j < 16; j++) {
                    float4 vv = Vs[(s << 4) + j];
                    a4[j].x += p * vv.x; a4[j].y += p * vv.y;
                    a4[j].z += p * vv.z; a4[j].w += p * vv.w;
                }
            }
        }
    }

    float inv = 1.f / l;
    float4* op = (float4*)(ob + (size_t)t * oldd);
    #pragma unroll
    for (int j = 0; j < 16; j++) {
        float4 o4 = a4[j];
        o4.x *= inv; o4.y *= inv; o4.z *= inv; o4.w *= inv;
        op[j] = o4;
    }
}

// ---------------- orchestration --------------------------------------------
extern "C" void kernel_launch(void* const* d_in, const int* in_sizes, int n_in,
                              void* d_out, int out_size) {
    const float* x      = (const float*)d_in[0];
    const float* ximg   = (const float*)d_in[1];
    const float* ln1g   = (const float*)d_in[2];
    const float* ln1b   = (const float*)d_in[3];
    const float* ln2g   = (const float*)d_in[4];
    const float* ln2b   = (const float*)d_in[5];
    const float* Wattn  = (const float*)d_in[6];
    const float* battn  = (const float*)d_in[7];
    const float* Waproj = (const float*)d_in[8];
    const float* baproj = (const float*)d_in[9];
    const float* Wq     = (const float*)d_in[10];
    const float* bq     = (const float*)d_in[11];
    const float* Wk     = (const float*)d_in[12];
    const float* bk     = (const float*)d_in[13];
    const float* Wv     = (const float*)d_in[14];
    const float* bv     = (const float*)d_in[15];
    const float* Wcproj = (const float*)d_in[16];
    const float* bcproj = (const float*)d_in[17];
    const float* Wfc    = (const float*)d_in[18];
    const float* bfc    = (const float*)d_in[19];
    const float* Wmproj = (const float*)d_in[20];
    const float* bmproj = (const float*)d_in[21];
    float* out = (float*)d_out;

    float *ph, *pqkv, *pattn, *px, *pq2, *pk2, *pv2, *pff;
    cudaGetSymbolAddress((void**)&ph,    g_h);
    cudaGetSymbolAddress((void**)&pqkv,  g_qkv);
    cudaGetSymbolAddress((void**)&pattn, g_attn);
    cudaGetSymbolAddress((void**)&px,    g_x);
    cudaGetSymbolAddress((void**)&pq2,   g_q2);
    cudaGetSymbolAddress((void**)&pk2,   g_k2);
    cudaGetSymbolAddress((void**)&pv2,   g_v2);
    cudaGetSymbolAddress((void**)&pff,   g_ff);

    const int M  = Bz * Tz;    // 8192
    const int Mi = Bz * TIz;   // 2048

    // --- causal self-attention ---
    ln_kernel<<<M, 256>>>(x, ln1g, ln1b, ph);
    sgemm<<<dim3(3 * Cz / BN, M / BM), 256>>>(ph, Wattn, battn, nullptr, pqkv,
                                              M, 3 * Cz, Cz, 0);
    attn_kernel<true><<<dim3(Tz / 128, Bz * Hz), 128>>>(
        pqkv, 3 * Cz, pqkv + Cz, 3 * Cz, pqkv + 2 * Cz, 3 * Cz,
        pattn, Cz, Tz, Tz);
    sgemm<<<dim3(Cz / BN, M / BM), 256>>>(pattn, Waproj, baproj, x, px,
                                          M, Cz, Cz, 0);

    // --- cross-attention ---
    ln_kernel<<<M, 256>>>(px, ln1g, ln1b, ph);
    sgemm<<<dim3(Cz / BN, M / BM), 256>>>(ph, Wq, bq, nullptr, pq2, M, Cz, Cz, 0);
    sgemm<<<dim3(Cz / BN, Mi / BM), 256>>>(ximg, Wk, bk, nullptr, pk2, Mi, Cz, Cz, 0);
    sgemm<<<dim3(Cz / BN, Mi / BM), 256>>>(ximg, Wv, bv, nullptr, pv2, Mi, Cz, Cz, 0);
    attn_kernel<false><<<dim3(Tz / 128, Bz * Hz), 128>>>(
        pq2, Cz, pk2, Cz, pv2, Cz, pattn, Cz, Tz, TIz);
    sgemm<<<dim3(Cz / BN, M / BM), 256>>>(pattn, Wcproj, bcproj, px, px,
                                          M, Cz, Cz, 0);

    // --- MLP ---
    ln_kernel<<<M, 256>>>(px, ln2g, ln2b, ph);
    sgemm<<<dim3(FFz / BN, M / BM), 256>>>(ph, Wfc, bfc, nullptr, pff,
                                           M, FFz, Cz, 1);
    sgemm<<<dim3(Cz / BN, M / BM), 256>>>(pff, Wmproj, bmproj, px, out,
                                          M, Cz, FFz, 0);
}

// round 3
// speedup vs baseline: 2.1668x; 2.1668x over previous
#include <cuda_runtime.h>
#include <cuda_bf16.h>
#include <stdint.h>
#include <math.h>

// Problem dims
#define Bz  8
#define Tz  1024
#define Cz  1024
#define Hz  16
#define Dz  64
#define TIz 256
#define FFz 4096

// ---------------- scratch (device globals; no allocation allowed) ----------
__device__ float g_h   [Bz * Tz * Cz];
__device__ float g_qkv [Bz * Tz * 3 * Cz];
__device__ float g_attn[Bz * Tz * Cz];
__device__ float g_x   [Bz * Tz * Cz];
__device__ float g_q2  [Bz * Tz * Cz];
__device__ float g_k2  [Bz * TIz * Cz];
__device__ float g_v2  [Bz * TIz * Cz];
__device__ float g_ff  [Bz * Tz * FFz];

// ---------------- LayerNorm --------------------------------------------------
__global__ void ln_kernel(const float* __restrict__ x,
                          const float* __restrict__ gam,
                          const float* __restrict__ bet,
                          float* __restrict__ out) {
    int row = blockIdx.x;
    const float4* xp = (const float4*)(x + (size_t)row * Cz);
    float4 v = xp[threadIdx.x];
    float s  = v.x + v.y + v.z + v.w;
    float sq = v.x * v.x + v.y * v.y + v.z * v.z + v.w * v.w;

    __shared__ float rs[8], rq[8];
    #pragma unroll
    for (int o = 16; o > 0; o >>= 1) {
        s  += __shfl_down_sync(0xffffffffu, s,  o);
        sq += __shfl_down_sync(0xffffffffu, sq, o);
    }
    int wid = threadIdx.x >> 5, lid = threadIdx.x & 31;
    if (lid == 0) { rs[wid] = s; rq[wid] = sq; }
    __syncthreads();
    if (wid == 0) {
        s  = (lid < 8) ? rs[lid] : 0.f;
        sq = (lid < 8) ? rq[lid] : 0.f;
        #pragma unroll
        for (int o = 4; o > 0; o >>= 1) {
            s  += __shfl_down_sync(0xffffffffu, s,  o);
            sq += __shfl_down_sync(0xffffffffu, sq, o);
        }
        if (lid == 0) { rs[0] = s; rq[0] = sq; }
    }
    __syncthreads();
    float mu  = rs[0] * (1.0f / Cz);
    float var = rq[0] * (1.0f / Cz) - mu * mu;
    float inv = rsqrtf(var + 1e-5f);

    float4 gv = ((const float4*)gam)[threadIdx.x];
    float4 bv = ((const float4*)bet)[threadIdx.x];
    float4 o4;
    o4.x = (v.x - mu) * inv * gv.x + bv.x;
    o4.y = (v.y - mu) * inv * gv.y + bv.y;
    o4.z = (v.z - mu) * inv * gv.z + bv.z;
    o4.w = (v.w - mu) * inv * gv.w + bv.w;
    ((float4*)(out + (size_t)row * Cz))[threadIdx.x] = o4;
}

// ---------------- helpers ----------------------------------------------------
__device__ __forceinline__ unsigned short f2bf(float v) {
    __nv_bfloat16 b = __float2bfloat16_rn(v);
    return *reinterpret_cast<unsigned short*>(&b);
}
__device__ __forceinline__ float bf2f(unsigned short u) {
    return __uint_as_float(((unsigned)u) << 16);
}
__device__ __forceinline__ float gelu_tanh(float v) {
    float u = 0.7978845608028654f * (v + 0.044715f * v * v * v);
    float t;
    asm("tanh.approx.f32 %0, %1;" : "=f"(t) : "f"(u));
    return 0.5f * v * (1.0f + t);
}

#define LDSM_X4(r0, r1, r2, r3, addr) \
    asm volatile("ldmatrix.sync.aligned.m8n8.x4.shared.b16 {%0,%1,%2,%3}, [%4];" \
                 : "=r"(r0), "=r"(r1), "=r"(r2), "=r"(r3) : "r"(addr))
#define LDSM_X2T(r0, r1, addr) \
    asm volatile("ldmatrix.sync.aligned.m8n8.x2.trans.shared.b16 {%0,%1}, [%2];" \
                 : "=r"(r0), "=r"(r1) : "r"(addr))
#define MMA16816(c, a, b) \
    asm volatile("mma.sync.aligned.m16n8k16.row.col.f32.bf16.bf16.f32 " \
                 "{%0,%1,%2,%3}, {%4,%5,%6,%7}, {%8,%9}, {%0,%1,%2,%3};" \
                 : "+f"(c[0]), "+f"(c[1]), "+f"(c[2]), "+f"(c[3]) \
                 : "r"(a[0]), "r"(a[1]), "r"(a[2]), "r"(a[3]), "r"(b[0]), "r"(b[1]))

// ---------------- bf16-split tensor-core GEMM --------------------------------
// C[M,N] = A[M,K] @ B[K,N] + bias (+ Res) (+ gelu)
// Split: a = ah + al (bf16 each); acc += AhBh + AhBl + AlBh  (error ~2^-16)
// Tile 128x128x32, 256 threads = 8 warps (2x4), warp tile 64x32.
#define ASTR 40    // A smem row stride (bf16 elems), rows=128, cols=32
#define BSTR 136   // B smem row stride (bf16 elems), rows=32,  cols=128

__global__ __launch_bounds__(256)
void gemm_bf16(const float* __restrict__ A, const float* __restrict__ Bm,
               const float* __restrict__ bias, const float* __restrict__ Res,
               float* __restrict__ Cm, int M, int N, int K, int act) {
    __shared__ __align__(16) unsigned short AsH[128 * ASTR];
    __shared__ __align__(16) unsigned short AsL[128 * ASTR];
    __shared__ __align__(16) unsigned short BsH[32 * BSTR];
    __shared__ __align__(16) unsigned short BsL[32 * BSTR];

    const int tid = threadIdx.x;
    const int lane = tid & 31;
    const int wid = tid >> 5;
    const int wm = wid >> 2;          // 0..1
    const int wn = wid & 3;           // 0..3
    const int bm = blockIdx.y * 128, bn = blockIdx.x * 128;

    float acc[4][4][4];
    #pragma unroll
    for (int i = 0; i < 4; i++)
        #pragma unroll
        for (int j = 0; j < 4; j++)
            #pragma unroll
            for (int e = 0; e < 4; e++) acc[i][j][e] = 0.f;

    // global load mapping (4 float4 each for A and B)
    const int a_row = tid >> 1;              // via idx = i*256+tid: row=idx>>3
    // A: idx = i*256 + tid ; row = idx>>3, c4 = idx&7
    // B: idx = i*256 + tid ; k   = idx>>5, c4 = idx&31

    // ldmatrix lane addressing
    const int a_r = lane & 15;
    const int a_c = (lane >> 4) * 8;
    uint32_t asH = (uint32_t)__cvta_generic_to_shared(AsH);
    uint32_t asL = (uint32_t)__cvta_generic_to_shared(AsL);
    uint32_t bsH = (uint32_t)__cvta_generic_to_shared(BsH);
    uint32_t bsL = (uint32_t)__cvta_generic_to_shared(BsL);

    const int nk = K >> 5;
    float4 aR[4], bR[4];

    // prefetch tile 0
    #pragma unroll
    for (int i = 0; i < 4; i++) {
        int idx = i * 256 + tid;
        int r = idx >> 3, c4 = idx & 7;
        aR[i] = *(const float4*)(A + (size_t)(bm + r) * K + c4 * 4);
        int k = idx >> 5, bc4 = idx & 31;
        bR[i] = *(const float4*)(Bm + (size_t)k * N + bn + bc4 * 4);
    }

    for (int kt = 0; kt < nk; kt++) {
        // store prefetched tile to smem (hi/lo split)
        #pragma unroll
        for (int i = 0; i < 4; i++) {
            int idx = i * 256 + tid;
            int r = idx >> 3, c4 = idx & 7;
            float va[4] = {aR[i].x, aR[i].y, aR[i].z, aR[i].w};
            uint32_t ph0, ph1, pl0, pl1;
            {
                unsigned short h0 = f2bf(va[0]), h1 = f2bf(va[1]);
                unsigned short h2 = f2bf(va[2]), h3 = f2bf(va[3]);
                unsigned short l0 = f2bf(va[0] - bf2f(h0));
                unsigned short l1 = f2bf(va[1] - bf2f(h1));
                unsigned short l2 = f2bf(va[2] - bf2f(h2));
                unsigned short l3 = f2bf(va[3] - bf2f(h3));
                ph0 = (uint32_t)h0 | ((uint32_t)h1 << 16);
                ph1 = (uint32_t)h2 | ((uint32_t)h3 << 16);
                pl0 = (uint32_t)l0 | ((uint32_t)l1 << 16);
                pl1 = (uint32_t)l2 | ((uint32_t)l3 << 16);
            }
            int off = (r * ASTR + c4 * 4) >> 1;
            ((uint32_t*)AsH)[off] = ph0; ((uint32_t*)AsH)[off + 1] = ph1;
            ((uint32_t*)AsL)[off] = pl0; ((uint32_t*)AsL)[off + 1] = pl1;

            int k = idx >> 5, bc4 = idx & 31;
            float vb[4] = {bR[i].x, bR[i].y, bR[i].z, bR[i].w};
            {
                unsigned short h0 = f2bf(vb[0]), h1 = f2bf(vb[1]);
                unsigned short h2 = f2bf(vb[2]), h3 = f2bf(vb[3]);
                unsigned short l0 = f2bf(vb[0] - bf2f(h0));
                unsigned short l1 = f2bf(vb[1] - bf2f(h1));
                unsigned short l2 = f2bf(vb[2] - bf2f(h2));
                unsigned short l3 = f2bf(vb[3] - bf2f(h3));
                ph0 = (uint32_t)h0 | ((uint32_t)h1 << 16);
                ph1 = (uint32_t)h2 | ((uint32_t)h3 << 16);
                pl0 = (uint32_t)l0 | ((uint32_t)l1 << 16);
                pl1 = (uint32_t)l2 | ((uint32_t)l3 << 16);
            }
            int boff = (k * BSTR + bc4 * 4) >> 1;
            ((uint32_t*)BsH)[boff] = ph0; ((uint32_t*)BsH)[boff + 1] = ph1;
            ((uint32_t*)BsL)[boff] = pl0; ((uint32_t*)BsL)[boff + 1] = pl1;
        }
        __syncthreads();

        // prefetch next tile
        if (kt + 1 < nk) {
            int kbase = (kt + 1) * 32;
            #pragma unroll
            for (int i = 0; i < 4; i++) {
                int idx = i * 256 + tid;
                int r = idx >> 3, c4 = idx & 7;
                aR[i] = *(const float4*)(A + (size_t)(bm + r) * K + kbase + c4 * 4);
                int k = idx >> 5, bc4 = idx & 31;
                bR[i] = *(const float4*)(Bm + (size_t)(kbase + k) * N + bn + bc4 * 4);
            }
        }

        // compute: 2 k-steps of 16
        #pragma unroll
        for (int ks = 0; ks < 2; ks++) {
            uint32_t ah[4][4], al[4][4], bh[4][2], bl[4][2];
            #pragma unroll
            for (int mt = 0; mt < 4; mt++) {
                uint32_t off = (uint32_t)(((wm * 64 + mt * 16 + a_r) * ASTR
                                           + ks * 16 + a_c) * 2);
                LDSM_X4(ah[mt][0], ah[mt][1], ah[mt][2], ah[mt][3], asH + off);
                LDSM_X4(al[mt][0], al[mt][1], al[mt][2], al[mt][3], asL + off);
            }
            #pragma unroll
            for (int nt = 0; nt < 4; nt++) {
                uint32_t off = (uint32_t)(((ks * 16 + (lane & 15)) * BSTR
                                           + wn * 32 + nt * 8) * 2);
                LDSM_X2T(bh[nt][0], bh[nt][1], bsH + off);
                LDSM_X2T(bl[nt][0], bl[nt][1], bsL + off);
            }
            #pragma unroll
            for (int mt = 0; mt < 4; mt++)
                #pragma unroll
                for (int nt = 0; nt < 4; nt++) {
                    MMA16816(acc[mt][nt], ah[mt], bh[nt]);
                    MMA16816(acc[mt][nt], ah[mt], bl[nt]);
                    MMA16816(acc[mt][nt], al[mt], bh[nt]);
                }
        }
        __syncthreads();
    }

    // epilogue
    int crow = lane >> 2;          // 0..7
    int ccol = (lane & 3) * 2;     // 0,2,4,6
    #pragma unroll
    for (int mt = 0; mt < 4; mt++) {
        #pragma unroll
        for (int nt = 0; nt < 4; nt++) {
            int col = bn + wn * 32 + nt * 8 + ccol;
            float b0 = bias[col], b1 = bias[col + 1];
            #pragma unroll
            for (int half = 0; half < 2; half++) {
                int row = bm + wm * 64 + mt * 16 + crow + half * 8;
                size_t off = (size_t)row * N + col;
                float c0 = acc[mt][nt][half * 2 + 0] + b0;
                float c1 = acc[mt][nt][half * 2 + 1] + b1;
                if (Res) {
                    float2 r = *(const float2*)(Res + off);
                    c0 += r.x; c1 += r.y;
                }
                if (act) { c0 = gelu_tanh(c0); c1 = gelu_tanh(c1); }
                *(float2*)(Cm + off) = make_float2(c0, c1);
            }
        }
    }
}

// ---------------- Flash attention: 1 query row per thread --------------------
template <bool CAUSAL>
__global__ __launch_bounds__(128)
void attn_kernel(const float* __restrict__ Q, int qld,
                 const float* __restrict__ K, int kld,
                 const float* __restrict__ V, int vld,
                 float* __restrict__ O, int oldd,
                 int Tq, int S) {
    __shared__ float4 Ks[64 * 16];
    __shared__ float4 Vs[64 * 16];

    int bh = blockIdx.y;
    int b = bh >> 4, h = bh & 15;
    const float* qb = Q + (size_t)b * Tq * qld + h * Dz;
    const float* kb = K + (size_t)b * S * kld + h * Dz;
    const float* vb = V + (size_t)b * S * vld + h * Dz;
    float* ob = O + (size_t)b * Tq * oldd + h * Dz;

    int t = blockIdx.x * 128 + threadIdx.x;

    float4 q4[16], a4[16];
    const float4* qp = (const float4*)(qb + (size_t)t * qld);
    #pragma unroll
    for (int j = 0; j < 16; j++) {
        q4[j] = qp[j];
        a4[j] = make_float4(0.f, 0.f, 0.f, 0.f);
    }
    float m = -1e30f, l = 0.f;

    int smax = CAUSAL ? (blockIdx.x * 128 + 128) : S;
    for (int s0 = 0; s0 < smax; s0 += 64) {
        __syncthreads();
        for (int i = threadIdx.x; i < 64 * 16; i += 128) {
            int r = i >> 4, c = i & 15;
            Ks[i] = ((const float4*)(kb + (size_t)(s0 + r) * kld))[c];
            Vs[i] = ((const float4*)(vb + (size_t)(s0 + r) * vld))[c];
        }
        __syncthreads();
        int send = min(64, smax - s0);
        for (int s = 0; s < send; s++) {
            bool active = !(CAUSAL && (s0 + s) > t);
            if (active) {
                float dot = 0.f;
                #pragma unroll
                for (int j = 0; j < 16; j++) {
                    float4 kk = Ks[(s << 4) + j];
                    dot += q4[j].x * kk.x + q4[j].y * kk.y +
                           q4[j].z * kk.z + q4[j].w * kk.w;
                }
                dot *= 0.125f;
                float mn = fmaxf(m, dot);
                float p = __expf(dot - mn);
                if (mn > m) {
                    float sc = __expf(m - mn);
                    l *= sc;
                    #pragma unroll
                    for (int j = 0; j < 16; j++) {
                        a4[j].x *= sc; a4[j].y *= sc;
                        a4[j].z *= sc; a4[j].w *= sc;
                    }
                    m = mn;
                }
                l += p;
                #pragma unroll
                for (int j = 0; j < 16; j++) {
                    float4 vv = Vs[(s << 4) + j];
                    a4[j].x += p * vv.x; a4[j].y += p * vv.y;
                    a4[j].z += p * vv.z; a4[j].w += p * vv.w;
                }
            }
        }
    }

    float inv = 1.f / l;
    float4* op = (float4*)(ob + (size_t)t * oldd);
    #pragma unroll
    for (int j = 0; j < 16; j++) {
        float4 o4 = a4[j];
        o4.x *= inv; o4.y *= inv; o4.z *= inv; o4.w *= inv;
        op[j] = o4;
    }
}

// ---------------- orchestration ----------------------------------------------
extern "C" void kernel_launch(void* const* d_in, const int* in_sizes, int n_in,
                              void* d_out, int out_size) {
    const float* x      = (const float*)d_in[0];
    const float* ximg   = (const float*)d_in[1];
    const float* ln1g   = (const float*)d_in[2];
    const float* ln1b   = (const float*)d_in[3];
    const float* ln2g   = (const float*)d_in[4];
    const float* ln2b   = (const float*)d_in[5];
    const float* Wattn  = (const float*)d_in[6];
    const float* battn  = (const float*)d_in[7];
    const float* Waproj = (const float*)d_in[8];
    const float* baproj = (const float*)d_in[9];
    const float* Wq     = (const float*)d_in[10];
    const float* bq     = (const float*)d_in[11];
    const float* Wk     = (const float*)d_in[12];
    const float* bk     = (const float*)d_in[13];
    const float* Wv     = (const float*)d_in[14];
    const float* bv     = (const float*)d_in[15];
    const float* Wcproj = (const float*)d_in[16];
    const float* bcproj = (const float*)d_in[17];
    const float* Wfc    = (const float*)d_in[18];
    const float* bfc    = (const float*)d_in[19];
    const float* Wmproj = (const float*)d_in[20];
    const float* bmproj = (const float*)d_in[21];
    float* out = (float*)d_out;

    float *ph, *pqkv, *pattn, *px, *pq2, *pk2, *pv2, *pff;
    cudaGetSymbolAddress((void**)&ph,    g_h);
    cudaGetSymbolAddress((void**)&pqkv,  g_qkv);
    cudaGetSymbolAddress((void**)&pattn, g_attn);
    cudaGetSymbolAddress((void**)&px,    g_x);
    cudaGetSymbolAddress((void**)&pq2,   g_q2);
    cudaGetSymbolAddress((void**)&pk2,   g_k2);
    cudaGetSymbolAddress((void**)&pv2,   g_v2);
    cudaGetSymbolAddress((void**)&pff,   g_ff);

    const int M  = Bz * Tz;    // 8192
    const int Mi = Bz * TIz;   // 2048

    // --- causal self-attention ---
    ln_kernel<<<M, 256>>>(x, ln1g, ln1b, ph);
    gemm_bf16<<<dim3(3 * Cz / 128, M / 128), 256>>>(ph, Wattn, battn, nullptr,
                                                    pqkv, M, 3 * Cz, Cz, 0);
    attn_kernel<true><<<dim3(Tz / 128, Bz * Hz), 128>>>(
        pqkv, 3 * Cz, pqkv + Cz, 3 * Cz, pqkv + 2 * Cz, 3 * Cz,
        pattn, Cz, Tz, Tz);
    gemm_bf16<<<dim3(Cz / 128, M / 128), 256>>>(pattn, Waproj, baproj, x, px,
                                                M, Cz, Cz, 0);

    // --- cross-attention ---
    ln_kernel<<<M, 256>>>(px, ln1g, ln1b, ph);
    gemm_bf16<<<dim3(Cz / 128, M / 128), 256>>>(ph, Wq, bq, nullptr, pq2,
                                                M, Cz, Cz, 0);
    gemm_bf16<<<dim3(Cz / 128, Mi / 128), 256>>>(ximg, Wk, bk, nullptr, pk2,
                                                 Mi, Cz, Cz, 0);
    gemm_bf16<<<dim3(Cz / 128, Mi / 128), 256>>>(ximg, Wv, bv, nullptr, pv2,
                                                 Mi, Cz, Cz, 0);
    attn_kernel<false><<<dim3(Tz / 128, Bz * Hz), 128>>>(
        pq2, Cz, pk2, Cz, pv2, Cz, pattn, Cz, Tz, TIz);
    gemm_bf16<<<dim3(Cz / 128, M / 128), 256>>>(pattn, Wcproj, bcproj, px, px,
                                                M, Cz, Cz, 0);

    // --- MLP ---
    ln_kernel<<<M, 256>>>(px, ln2g, ln2b, ph);
    gemm_bf16<<<dim3(FFz / 128, M / 128), 256>>>(ph, Wfc, bfc, nullptr, pff,
                                                 M, FFz, Cz, 1);
    gemm_bf16<<<dim3(Cz / 128, M / 128), 256>>>(pff, Wmproj, bmproj, px, out,
                                                M, Cz, FFz, 0);
}

// round 4
// speedup vs baseline: 2.5075x; 1.1573x over previous
#include <cuda_runtime.h>
#include <cuda_bf16.h>
#include <stdint.h>
#include <math.h>

// Problem dims
#define Bz  8
#define Tz  1024
#define Cz  1024
#define Hz  16
#define Dz  64
#define TIz 256
#define FFz 4096

typedef unsigned short ushort_t;

// ---------------- scratch (device globals) -----------------------------------
// weight splits: one arena, offsets below (16M elems)
#define OFF_WATTN  0
#define OFF_WAPROJ 3145728
#define OFF_WQ     4194304
#define OFF_WK     5242880
#define OFF_WV     6291456
#define OFF_WCPROJ 7340032
#define OFF_WFC    8388608
#define OFF_WMPROJ 12582912
#define W_TOTAL    16777216

__device__ ushort_t g_wh[W_TOTAL];
__device__ ushort_t g_wl[W_TOTAL];

__device__ ushort_t g_hh [Bz * Tz * Cz];   // LN out split
__device__ ushort_t g_hl [Bz * Tz * Cz];
__device__ ushort_t g_ah [Bz * Tz * Cz];   // attention out split
__device__ ushort_t g_al [Bz * Tz * Cz];
__device__ ushort_t g_xih[Bz * TIz * Cz];  // ximg split
__device__ ushort_t g_xil[Bz * TIz * Cz];
__device__ ushort_t g_ffh[Bz * Tz * FFz];  // MLP hidden split
__device__ ushort_t g_ffl[Bz * Tz * FFz];

__device__ float g_qkv[Bz * Tz * 3 * Cz];
__device__ float g_x  [Bz * Tz * Cz];      // running residual
__device__ float g_q2 [Bz * Tz * Cz];
__device__ float g_k2 [Bz * TIz * Cz];
__device__ float g_v2 [Bz * TIz * Cz];

// ---------------- helpers ----------------------------------------------------
__device__ __forceinline__ ushort_t f2bf(float v) {
    __nv_bfloat16 b = __float2bfloat16_rn(v);
    return *reinterpret_cast<ushort_t*>(&b);
}
__device__ __forceinline__ float bf2f(ushort_t u) {
    return __uint_as_float(((unsigned)u) << 16);
}
__device__ __forceinline__ float gelu_tanh(float v) {
    float u = 0.7978845608028654f * (v + 0.044715f * v * v * v);
    float t;
    asm("tanh.approx.f32 %0, %1;" : "=f"(t) : "f"(u));
    return 0.5f * v * (1.0f + t);
}

#define LDSM_X4(r0, r1, r2, r3, addr) \
    asm volatile("ldmatrix.sync.aligned.m8n8.x4.shared.b16 {%0,%1,%2,%3}, [%4];" \
                 : "=r"(r0), "=r"(r1), "=r"(r2), "=r"(r3) : "r"(addr))
#define LDSM_X2T(r0, r1, addr) \
    asm volatile("ldmatrix.sync.aligned.m8n8.x2.trans.shared.b16 {%0,%1}, [%2];" \
                 : "=r"(r0), "=r"(r1) : "r"(addr))
#define MMA16816(c, a, b) \
    asm volatile("mma.sync.aligned.m16n8k16.row.col.f32.bf16.bf16.f32 " \
                 "{%0,%1,%2,%3}, {%4,%5,%6,%7}, {%8,%9}, {%0,%1,%2,%3};" \
                 : "+f"(c[0]), "+f"(c[1]), "+f"(c[2]), "+f"(c[3]) \
                 : "r"(a[0]), "r"(a[1]), "r"(a[2]), "r"(a[3]), "r"(b[0]), "r"(b[1]))
#define CP16(dst, src) \
    asm volatile("cp.async.cg.shared.global [%0], [%1], 16;" :: "r"(dst), "l"(src))
#define CPCOMMIT() asm volatile("cp.async.commit_group;")
#define CPWAIT(n)  asm volatile("cp.async.wait_group %0;" :: "n"(n))

// ---------------- split conversion (fp32 -> bf16 hi/lo) ----------------------
__global__ void split_kernel(const float* __restrict__ s,
                             ushort_t* __restrict__ h,
                             ushort_t* __restrict__ l, int n4) {
    int i = blockIdx.x * 256 + threadIdx.x;
    if (i < n4) {
        float4 v = ((const float4*)s)[i];
        ushort4 hh, ll;
        hh.x = f2bf(v.x); ll.x = f2bf(v.x - bf2f(hh.x));
        hh.y = f2bf(v.y); ll.y = f2bf(v.y - bf2f(hh.y));
        hh.z = f2bf(v.z); ll.z = f2bf(v.z - bf2f(hh.z));
        hh.w = f2bf(v.w); ll.w = f2bf(v.w - bf2f(hh.w));
        ((ushort4*)h)[i] = hh;
        ((ushort4*)l)[i] = ll;
    }
}

// ---------------- LayerNorm -> split output ----------------------------------
__global__ void ln_kernel(const float* __restrict__ x,
                          const float* __restrict__ gam,
                          const float* __restrict__ bet,
                          ushort_t* __restrict__ oh,
                          ushort_t* __restrict__ ol) {
    int row = blockIdx.x;
    const float4* xp = (const float4*)(x + (size_t)row * Cz);
    float4 v = xp[threadIdx.x];
    float s  = v.x + v.y + v.z + v.w;
    float sq = v.x * v.x + v.y * v.y + v.z * v.z + v.w * v.w;

    __shared__ float rs[8], rq[8];
    #pragma unroll
    for (int o = 16; o > 0; o >>= 1) {
        s  += __shfl_down_sync(0xffffffffu, s,  o);
        sq += __shfl_down_sync(0xffffffffu, sq, o);
    }
    int wid = threadIdx.x >> 5, lid = threadIdx.x & 31;
    if (lid == 0) { rs[wid] = s; rq[wid] = sq; }
    __syncthreads();
    if (wid == 0) {
        s  = (lid < 8) ? rs[lid] : 0.f;
        sq = (lid < 8) ? rq[lid] : 0.f;
        #pragma unroll
        for (int o = 4; o > 0; o >>= 1) {
            s  += __shfl_down_sync(0xffffffffu, s,  o);
            sq += __shfl_down_sync(0xffffffffu, sq, o);
        }
        if (lid == 0) { rs[0] = s; rq[0] = sq; }
    }
    __syncthreads();
    float mu  = rs[0] * (1.0f / Cz);
    float var = rq[0] * (1.0f / Cz) - mu * mu;
    float inv = rsqrtf(var + 1e-5f);

    float4 gv = ((const float4*)gam)[threadIdx.x];
    float4 bv = ((const float4*)bet)[threadIdx.x];
    float4 o4;
    o4.x = (v.x - mu) * inv * gv.x + bv.x;
    o4.y = (v.y - mu) * inv * gv.y + bv.y;
    o4.z = (v.z - mu) * inv * gv.z + bv.z;
    o4.w = (v.w - mu) * inv * gv.w + bv.w;
    ushort4 hh, ll;
    hh.x = f2bf(o4.x); ll.x = f2bf(o4.x - bf2f(hh.x));
    hh.y = f2bf(o4.y); ll.y = f2bf(o4.y - bf2f(hh.y));
    hh.z = f2bf(o4.z); ll.z = f2bf(o4.z - bf2f(hh.z));
    hh.w = f2bf(o4.w); ll.w = f2bf(o4.w - bf2f(hh.w));
    ((ushort4*)(oh + (size_t)row * Cz))[threadIdx.x] = hh;
    ((ushort4*)(ol + (size_t)row * Cz))[threadIdx.x] = ll;
}

// ---------------- bf16-split tensor-core GEMM (pipelined) --------------------
// C[M,N] = Ah+Al @ Bh+Bl (3-term) + bias (+Res) (+gelu)
// Tile 128x128x32, 512 threads = 16 warps (4x4), warp tile 32x32.
// Operands pre-split in gmem (bf16 hi/lo). cp.async double buffer.
#define ASTR 40
#define BSTR 136
#define A_T  (128 * ASTR)             // elems per A plane
#define B_T  (32 * BSTR)              // elems per B plane
#define STG  (2 * A_T + 2 * B_T)      // elems per stage

__global__ __launch_bounds__(512)
void gemm_bs(const ushort_t* __restrict__ Ah, const ushort_t* __restrict__ Al,
             const ushort_t* __restrict__ Bh, const ushort_t* __restrict__ Bl,
             const float* __restrict__ bias, const float* __restrict__ Res,
             float* __restrict__ Cf, ushort_t* __restrict__ Ch,
             ushort_t* __restrict__ Cl, int M, int N, int K, int act) {
    extern __shared__ ushort_t smem[];

    const int tid = threadIdx.x;
    const int lane = tid & 31;
    const int wid = tid >> 5;
    const int wm = wid >> 2;          // 0..3
    const int wn = wid & 3;           // 0..3
    const int bm = blockIdx.y * 128, bn = blockIdx.x * 128;

    uint32_t sbase = (uint32_t)__cvta_generic_to_shared(smem);

    float acc[2][4][4];
    #pragma unroll
    for (int i = 0; i < 2; i++)
        #pragma unroll
        for (int j = 0; j < 4; j++)
            #pragma unroll
            for (int e = 0; e < 4; e++) acc[i][j][e] = 0.f;

    // cp.async mapping: 512 threads, each 1x16B per plane
    const int ar = tid >> 2, ac8 = (tid & 3) * 8;
    const int br = tid >> 4, bc8 = (tid & 15) * 8;
    const ushort_t* gAh = Ah + (size_t)(bm + ar) * K + ac8;
    const ushort_t* gAl = Al + (size_t)(bm + ar) * K + ac8;
    const ushort_t* gBh = Bh + (size_t)br * N + bn + bc8;
    const ushort_t* gBl = Bl + (size_t)br * N + bn + bc8;
    const uint32_t dA = sbase + (uint32_t)(ar * ASTR + ac8) * 2;
    const uint32_t dB = sbase + (uint32_t)(2 * A_T + br * BSTR + bc8) * 2;

    const int nk = K >> 5;

    auto issue = [&](int kt, int s) {
        uint32_t so = (uint32_t)(s * STG) * 2;
        CP16(dA + so,            gAh + kt * 32);
        CP16(dA + so + A_T * 2,  gAl + kt * 32);
        CP16(dB + so,            gBh + (size_t)kt * 32 * N);
        CP16(dB + so + B_T * 2,  gBl + (size_t)kt * 32 * N);
        CPCOMMIT();
    };

    issue(0, 0);

    const int a_r = lane & 15;
    const int a_c = (lane >> 4) * 8;

    for (int kt = 0; kt < nk; kt++) {
        if (kt + 1 < nk) { issue(kt + 1, (kt + 1) & 1); CPWAIT(1); }
        else             { CPWAIT(0); }
        __syncthreads();

        uint32_t s0 = sbase + (uint32_t)((kt & 1) * STG) * 2;
        #pragma unroll
        for (int ks = 0; ks < 2; ks++) {
            uint32_t ah[2][4], al[2][4], bh[4][2], bl[4][2];
            #pragma unroll
            for (int mt = 0; mt < 2; mt++) {
                uint32_t off = s0 + (uint32_t)(((wm * 32 + mt * 16 + a_r) * ASTR
                                               + ks * 16 + a_c) * 2);
                LDSM_X4(ah[mt][0], ah[mt][1], ah[mt][2], ah[mt][3], off);
                LDSM_X4(al[mt][0], al[mt][1], al[mt][2], al[mt][3], off + A_T * 2);
            }
            #pragma unroll
            for (int nt = 0; nt < 4; nt++) {
                uint32_t off = s0 + (uint32_t)((2 * A_T
                                                + (ks * 16 + a_r) * BSTR
                                                + wn * 32 + nt * 8) * 2);
                LDSM_X2T(bh[nt][0], bh[nt][1], off);
                LDSM_X2T(bl[nt][0], bl[nt][1], off + B_T * 2);
            }
            #pragma unroll
            for (int mt = 0; mt < 2; mt++)
                #pragma unroll
                for (int nt = 0; nt < 4; nt++) {
                    MMA16816(acc[mt][nt], ah[mt], bh[nt]);
                    MMA16816(acc[mt][nt], ah[mt], bl[nt]);
                    MMA16816(acc[mt][nt], al[mt], bh[nt]);
                }
        }
        __syncthreads();
    }

    // epilogue
    int crow = lane >> 2;
    int ccol = (lane & 3) * 2;
    #pragma unroll
    for (int mt = 0; mt < 2; mt++) {
        #pragma unroll
        for (int nt = 0; nt < 4; nt++) {
            int col = bn + wn * 32 + nt * 8 + ccol;
            float b0 = bias[col], b1 = bias[col + 1];
            #pragma unroll
            for (int half = 0; half < 2; half++) {
                int row = bm + wm * 32 + mt * 16 + crow + half * 8;
                size_t off = (size_t)row * N + col;
                float c0 = acc[mt][nt][half * 2 + 0] + b0;
                float c1 = acc[mt][nt][half * 2 + 1] + b1;
                if (Res) {
                    float2 r = *(const float2*)(Res + off);
                    c0 += r.x; c1 += r.y;
                }
                if (act) { c0 = gelu_tanh(c0); c1 = gelu_tanh(c1); }
                if (Cf) *(float2*)(Cf + off) = make_float2(c0, c1);
                if (Ch) {
                    ushort_t h0 = f2bf(c0), h1 = f2bf(c1);
                    ushort2 hh; hh.x = h0; hh.y = h1;
                    ushort2 ll;
                    ll.x = f2bf(c0 - bf2f(h0));
                    ll.y = f2bf(c1 - bf2f(h1));
                    *(ushort2*)(Ch + off) = hh;
                    *(ushort2*)(Cl + off) = ll;
                }
            }
        }
    }
}

// ---------------- Flash attention (fp32), split output -----------------------
template <bool CAUSAL>
__global__ __launch_bounds__(128)
void attn_kernel(const float* __restrict__ Q, int qld,
                 const float* __restrict__ K, int kld,
                 const float* __restrict__ V, int vld,
                 ushort_t* __restrict__ Oh, ushort_t* __restrict__ Ol,
                 int Tq, int S) {
    __shared__ float4 Ks[64 * 16];
    __shared__ float4 Vs[64 * 16];

    int bh = blockIdx.y;
    int b = bh >> 4, h = bh & 15;
    const float* qb = Q + (size_t)b * Tq * qld + h * Dz;
    const float* kb = K + (size_t)b * S * kld + h * Dz;
    const float* vb = V + (size_t)b * S * vld + h * Dz;
    ushort_t* obh = Oh + (size_t)b * Tq * Cz + h * Dz;
    ushort_t* obl = Ol + (size_t)b * Tq * Cz + h * Dz;

    int t = blockIdx.x * 128 + threadIdx.x;

    float4 q4[16], a4[16];
    const float4* qp = (const float4*)(qb + (size_t)t * qld);
    #pragma unroll
    for (int j = 0; j < 16; j++) {
        q4[j] = qp[j];
        a4[j] = make_float4(0.f, 0.f, 0.f, 0.f);
    }
    float m = -1e30f, l = 0.f;

    int smax = CAUSAL ? (blockIdx.x * 128 + 128) : S;
    for (int s0 = 0; s0 < smax; s0 += 64) {
        __syncthreads();
        for (int i = threadIdx.x; i < 64 * 16; i += 128) {
            int r = i >> 4, c = i & 15;
            Ks[i] = ((const float4*)(kb + (size_t)(s0 + r) * kld))[c];
            Vs[i] = ((const float4*)(vb + (size_t)(s0 + r) * vld))[c];
        }
        __syncthreads();
        int send = min(64, smax - s0);
        for (int s = 0; s < send; s++) {
            bool active = !(CAUSAL && (s0 + s) > t);
            if (active) {
                float dot = 0.f;
                #pragma unroll
                for (int j = 0; j < 16; j++) {
                    float4 kk = Ks[(s << 4) + j];
                    dot += q4[j].x * kk.x + q4[j].y * kk.y +
                           q4[j].z * kk.z + q4[j].w * kk.w;
                }
                dot *= 0.125f;
                float mn = fmaxf(m, dot);
                float p = __expf(dot - mn);
                if (mn > m) {
                    float sc = __expf(m - mn);
                    l *= sc;
                    #pragma unroll
                    for (int j = 0; j < 16; j++) {
                        a4[j].x *= sc; a4[j].y *= sc;
                        a4[j].z *= sc; a4[j].w *= sc;
                    }
                    m = mn;
                }
                l += p;
                #pragma unroll
                for (int j = 0; j < 16; j++) {
                    float4 vv = Vs[(s << 4) + j];
                    a4[j].x += p * vv.x; a4[j].y += p * vv.y;
                    a4[j].z += p * vv.z; a4[j].w += p * vv.w;
                }
            }
        }
    }

    float inv = 1.f / l;
    ushort4* oph = (ushort4*)(obh + (size_t)t * Cz);
    ushort4* opl = (ushort4*)(obl + (size_t)t * Cz);
    #pragma unroll
    for (int j = 0; j < 16; j++) {
        float4 o4 = a4[j];
        o4.x *= inv; o4.y *= inv; o4.z *= inv; o4.w *= inv;
        ushort4 hh, ll;
        hh.x = f2bf(o4.x); ll.x = f2bf(o4.x - bf2f(hh.x));
        hh.y = f2bf(o4.y); ll.y = f2bf(o4.y - bf2f(hh.y));
        hh.z = f2bf(o4.z); ll.z = f2bf(o4.z - bf2f(hh.z));
        hh.w = f2bf(o4.w); ll.w = f2bf(o4.w - bf2f(hh.w));
        oph[j] = hh;
        opl[j] = ll;
    }
}

// ---------------- orchestration ----------------------------------------------
extern "C" void kernel_launch(void* const* d_in, const int* in_sizes, int n_in,
                              void* d_out, int out_size) {
    const float* x      = (const float*)d_in[0];
    const float* ximg   = (const float*)d_in[1];
    const float* ln1g   = (const float*)d_in[2];
    const float* ln1b   = (const float*)d_in[3];
    const float* ln2g   = (const float*)d_in[4];
    const float* ln2b   = (const float*)d_in[5];
    const float* Wattn  = (const float*)d_in[6];
    const float* battn  = (const float*)d_in[7];
    const float* Waproj = (const float*)d_in[8];
    const float* baproj = (const float*)d_in[9];
    const float* Wq     = (const float*)d_in[10];
    const float* bq     = (const float*)d_in[11];
    const float* Wk     = (const float*)d_in[12];
    const float* bk     = (const float*)d_in[13];
    const float* Wv     = (const float*)d_in[14];
    const float* bv     = (const float*)d_in[15];
    const float* Wcproj = (const float*)d_in[16];
    const float* bcproj = (const float*)d_in[17];
    const float* Wfc    = (const float*)d_in[18];
    const float* bfc    = (const float*)d_in[19];
    const float* Wmproj = (const float*)d_in[20];
    const float* bmproj = (const float*)d_in[21];
    float* out = (float*)d_out;

    ushort_t *wh, *wl, *hh, *hl, *ah, *al, *xih, *xil, *ffh, *ffl;
    float *pqkv, *px, *pq2, *pk2, *pv2;
    cudaGetSymbolAddress((void**)&wh,   g_wh);
    cudaGetSymbolAddress((void**)&wl,   g_wl);
    cudaGetSymbolAddress((void**)&hh,   g_hh);
    cudaGetSymbolAddress((void**)&hl,   g_hl);
    cudaGetSymbolAddress((void**)&ah,   g_ah);
    cudaGetSymbolAddress((void**)&al,   g_al);
    cudaGetSymbolAddress((void**)&xih,  g_xih);
    cudaGetSymbolAddress((void**)&xil,  g_xil);
    cudaGetSymbolAddress((void**)&ffh,  g_ffh);
    cudaGetSymbolAddress((void**)&ffl,  g_ffl);
    cudaGetSymbolAddress((void**)&pqkv, g_qkv);
    cudaGetSymbolAddress((void**)&px,   g_x);
    cudaGetSymbolAddress((void**)&pq2,  g_q2);
    cudaGetSymbolAddress((void**)&pk2,  g_k2);
    cudaGetSymbolAddress((void**)&pv2,  g_v2);

    const int M  = Bz * Tz;    // 8192
    const int Mi = Bz * TIz;   // 2048
    const int SMEM = STG * 2 * 2;  // bytes (2 stages)

    cudaFuncSetAttribute(gemm_bs, cudaFuncAttributeMaxDynamicSharedMemorySize,
                         SMEM);

    // --- one-time (per call) operand splits ---
    #define SPLIT(src, dh, dl, n) \
        split_kernel<<<(n) / 1024, 256>>>(src, dh, dl, (n) / 4)
    SPLIT(Wattn,  wh + OFF_WATTN,  wl + OFF_WATTN,  3 * Cz * Cz);
    SPLIT(Waproj, wh + OFF_WAPROJ, wl + OFF_WAPROJ, Cz * Cz);
    SPLIT(Wq,     wh + OFF_WQ,     wl + OFF_WQ,     Cz * Cz);
    SPLIT(Wk,     wh + OFF_WK,     wl + OFF_WK,     Cz * Cz);
    SPLIT(Wv,     wh + OFF_WV,     wl + OFF_WV,     Cz * Cz);
    SPLIT(Wcproj, wh + OFF_WCPROJ, wl + OFF_WCPROJ, Cz * Cz);
    SPLIT(Wfc,    wh + OFF_WFC,    wl + OFF_WFC,    Cz * FFz);
    SPLIT(Wmproj, wh + OFF_WMPROJ, wl + OFF_WMPROJ, FFz * Cz);
    SPLIT(ximg,   xih,             xil,             Mi * Cz);

    // --- causal self-attention ---
    ln_kernel<<<M, 256>>>(x, ln1g, ln1b, hh, hl);
    gemm_bs<<<dim3(3 * Cz / 128, M / 128), 512, SMEM>>>(
        hh, hl, wh + OFF_WATTN, wl + OFF_WATTN, battn, nullptr,
        pqkv, nullptr, nullptr, M, 3 * Cz, Cz, 0);
    attn_kernel<true><<<dim3(Tz / 128, Bz * Hz), 128>>>(
        pqkv, 3 * Cz, pqkv + Cz, 3 * Cz, pqkv + 2 * Cz, 3 * Cz,
        ah, al, Tz, Tz);
    gemm_bs<<<dim3(Cz / 128, M / 128), 512, SMEM>>>(
        ah, al, wh + OFF_WAPROJ, wl + OFF_WAPROJ, baproj, x,
        px, nullptr, nullptr, M, Cz, Cz, 0);

    // --- cross-attention ---
    ln_kernel<<<M, 256>>>(px, ln1g, ln1b, hh, hl);
    gemm_bs<<<dim3(Cz / 128, M / 128), 512, SMEM>>>(
        hh, hl, wh + OFF_WQ, wl + OFF_WQ, bq, nullptr,
        pq2, nullptr, nullptr, M, Cz, Cz, 0);
    gemm_bs<<<dim3(Cz / 128, Mi / 128), 512, SMEM>>>(
        xih, xil, wh + OFF_WK, wl + OFF_WK, bk, nullptr,
        pk2, nullptr, nullptr, Mi, Cz, Cz, 0);
    gemm_bs<<<dim3(Cz / 128, Mi / 128), 512, SMEM>>>(
        xih, xil, wh + OFF_WV, wl + OFF_WV, bv, nullptr,
        pv2, nullptr, nullptr, Mi, Cz, Cz, 0);
    attn_kernel<false><<<dim3(Tz / 128, Bz * Hz), 128>>>(
        pq2, Cz, pk2, Cz, pv2, Cz, ah, al, Tz, TIz);
    gemm_bs<<<dim3(Cz / 128, M / 128), 512, SMEM>>>(
        ah, al, wh + OFF_WCPROJ, wl + OFF_WCPROJ, bcproj, px,
        px, nullptr, nullptr, M, Cz, Cz, 0);

    // --- MLP ---
    ln_kernel<<<M, 256>>>(px, ln2g, ln2b, hh, hl);
    gemm_bs<<<dim3(FFz / 128, M / 128), 512, SMEM>>>(
        hh, hl, wh + OFF_WFC, wl + OFF_WFC, bfc, nullptr,
        nullptr, ffh, ffl, M, FFz, Cz, 1);
    gemm_bs<<<dim3(Cz / 128, M / 128), 512, SMEM>>>(
        ffh, ffl, wh + OFF_WMPROJ, wl + OFF_WMPROJ, bmproj, px,
        out, nullptr, nullptr, M, Cz, FFz, 0);
}

// round 5
// speedup vs baseline: 3.4098x; 1.3598x over previous
#include <cuda_runtime.h>
#include <cuda_bf16.h>
#include <stdint.h>
#include <math.h>

// Problem dims
#define Bz  8
#define Tz  1024
#define Cz  1024
#define Hz  16
#define Dz  64
#define TIz 256
#define FFz 4096

typedef unsigned short ushort_t;

// ---------------- scratch (device globals) -----------------------------------
#define OFF_WATTN  0
#define OFF_WAPROJ 3145728
#define OFF_WQ     4194304
#define OFF_WK     5242880
#define OFF_WV     6291456
#define OFF_WCPROJ 7340032
#define OFF_WFC    8388608
#define OFF_WMPROJ 12582912
#define W_TOTAL    16777216

__device__ ushort_t g_wh[W_TOTAL];
__device__ ushort_t g_wl[W_TOTAL];

__device__ ushort_t g_hh  [Bz * Tz * Cz];
__device__ ushort_t g_hl  [Bz * Tz * Cz];
__device__ ushort_t g_ah  [Bz * Tz * Cz];
__device__ ushort_t g_al  [Bz * Tz * Cz];
__device__ ushort_t g_xih [Bz * TIz * Cz];
__device__ ushort_t g_xil [Bz * TIz * Cz];
__device__ ushort_t g_ffh [Bz * Tz * FFz];
__device__ ushort_t g_ffl [Bz * Tz * FFz];

__device__ ushort_t g_qkvh[Bz * Tz * 3 * Cz];
__device__ ushort_t g_qkvl[Bz * Tz * 3 * Cz];
__device__ ushort_t g_q2h [Bz * Tz * Cz];
__device__ ushort_t g_q2l [Bz * Tz * Cz];
__device__ ushort_t g_k2h [Bz * TIz * Cz];
__device__ ushort_t g_k2l [Bz * TIz * Cz];
__device__ ushort_t g_v2h [Bz * TIz * Cz];
__device__ ushort_t g_v2l [Bz * TIz * Cz];

__device__ float g_x[Bz * Tz * Cz];

// ---------------- helpers ----------------------------------------------------
__device__ __forceinline__ ushort_t f2bf(float v) {
    __nv_bfloat16 b = __float2bfloat16_rn(v);
    return *reinterpret_cast<ushort_t*>(&b);
}
__device__ __forceinline__ float bf2f(ushort_t u) {
    return __uint_as_float(((unsigned)u) << 16);
}
__device__ __forceinline__ uint32_t packbf(float a, float b) {
    return (uint32_t)f2bf(a) | ((uint32_t)f2bf(b) << 16);
}
__device__ __forceinline__ float ex2(float v) {
    float r;
    asm("ex2.approx.ftz.f32 %0, %1;" : "=f"(r) : "f"(v));
    return r;
}
__device__ __forceinline__ float gelu_tanh(float v) {
    float u = 0.7978845608028654f * (v + 0.044715f * v * v * v);
    float t;
    asm("tanh.approx.f32 %0, %1;" : "=f"(t) : "f"(u));
    return 0.5f * v * (1.0f + t);
}

#define LDSM_X4(r0, r1, r2, r3, addr) \
    asm volatile("ldmatrix.sync.aligned.m8n8.x4.shared.b16 {%0,%1,%2,%3}, [%4];" \
                 : "=r"(r0), "=r"(r1), "=r"(r2), "=r"(r3) : "r"(addr))
#define LDSM_X4T(r0, r1, r2, r3, addr) \
    asm volatile("ldmatrix.sync.aligned.m8n8.x4.trans.shared.b16 {%0,%1,%2,%3}, [%4];" \
                 : "=r"(r0), "=r"(r1), "=r"(r2), "=r"(r3) : "r"(addr))
#define LDSM_X2T(r0, r1, addr) \
    asm volatile("ldmatrix.sync.aligned.m8n8.x2.trans.shared.b16 {%0,%1}, [%2];" \
                 : "=r"(r0), "=r"(r1) : "r"(addr))
#define MMA16816(c, a, b) \
    asm volatile("mma.sync.aligned.m16n8k16.row.col.f32.bf16.bf16.f32 " \
                 "{%0,%1,%2,%3}, {%4,%5,%6,%7}, {%8,%9}, {%0,%1,%2,%3};" \
                 : "+f"(c[0]), "+f"(c[1]), "+f"(c[2]), "+f"(c[3]) \
                 : "r"(a[0]), "r"(a[1]), "r"(a[2]), "r"(a[3]), "r"(b[0]), "r"(b[1]))
#define MMA2(c, a, b0_, b1_) \
    asm volatile("mma.sync.aligned.m16n8k16.row.col.f32.bf16.bf16.f32 " \
                 "{%0,%1,%2,%3}, {%4,%5,%6,%7}, {%8,%9}, {%0,%1,%2,%3};" \
                 : "+f"(c[0]), "+f"(c[1]), "+f"(c[2]), "+f"(c[3]) \
                 : "r"(a[0]), "r"(a[1]), "r"(a[2]), "r"(a[3]), "r"(b0_), "r"(b1_))
#define CP16(dst, src) \
    asm volatile("cp.async.cg.shared.global [%0], [%1], 16;" :: "r"(dst), "l"(src))
#define CPCOMMIT() asm volatile("cp.async.commit_group;")
#define CPWAIT(n)  asm volatile("cp.async.wait_group %0;" :: "n"(n))

// ---------------- split conversion -------------------------------------------
__global__ void split_kernel(const float* __restrict__ s,
                             ushort_t* __restrict__ h,
                             ushort_t* __restrict__ l, int n4) {
    int i = blockIdx.x * 256 + threadIdx.x;
    if (i < n4) {
        float4 v = ((const float4*)s)[i];
        ushort4 hh, ll;
        hh.x = f2bf(v.x); ll.x = f2bf(v.x - bf2f(hh.x));
        hh.y = f2bf(v.y); ll.y = f2bf(v.y - bf2f(hh.y));
        hh.z = f2bf(v.z); ll.z = f2bf(v.z - bf2f(hh.z));
        hh.w = f2bf(v.w); ll.w = f2bf(v.w - bf2f(hh.w));
        ((ushort4*)h)[i] = hh;
        ((ushort4*)l)[i] = ll;
    }
}

// ---------------- LayerNorm -> split -----------------------------------------
__global__ void ln_kernel(const float* __restrict__ x,
                          const float* __restrict__ gam,
                          const float* __restrict__ bet,
                          ushort_t* __restrict__ oh,
                          ushort_t* __restrict__ ol) {
    int row = blockIdx.x;
    const float4* xp = (const float4*)(x + (size_t)row * Cz);
    float4 v = xp[threadIdx.x];
    float s  = v.x + v.y + v.z + v.w;
    float sq = v.x * v.x + v.y * v.y + v.z * v.z + v.w * v.w;

    __shared__ float rs[8], rq[8];
    #pragma unroll
    for (int o = 16; o > 0; o >>= 1) {
        s  += __shfl_down_sync(0xffffffffu, s,  o);
        sq += __shfl_down_sync(0xffffffffu, sq, o);
    }
    int wid = threadIdx.x >> 5, lid = threadIdx.x & 31;
    if (lid == 0) { rs[wid] = s; rq[wid] = sq; }
    __syncthreads();
    if (wid == 0) {
        s  = (lid < 8) ? rs[lid] : 0.f;
        sq = (lid < 8) ? rq[lid] : 0.f;
        #pragma unroll
        for (int o = 4; o > 0; o >>= 1) {
            s  += __shfl_down_sync(0xffffffffu, s,  o);
            sq += __shfl_down_sync(0xffffffffu, sq, o);
        }
        if (lid == 0) { rs[0] = s; rq[0] = sq; }
    }
    __syncthreads();
    float mu  = rs[0] * (1.0f / Cz);
    float var = rq[0] * (1.0f / Cz) - mu * mu;
    float inv = rsqrtf(var + 1e-5f);

    float4 gv = ((const float4*)gam)[threadIdx.x];
    float4 bv = ((const float4*)bet)[threadIdx.x];
    float4 o4;
    o4.x = (v.x - mu) * inv * gv.x + bv.x;
    o4.y = (v.y - mu) * inv * gv.y + bv.y;
    o4.z = (v.z - mu) * inv * gv.z + bv.z;
    o4.w = (v.w - mu) * inv * gv.w + bv.w;
    ushort4 hh, ll;
    hh.x = f2bf(o4.x); ll.x = f2bf(o4.x - bf2f(hh.x));
    hh.y = f2bf(o4.y); ll.y = f2bf(o4.y - bf2f(hh.y));
    hh.z = f2bf(o4.z); ll.z = f2bf(o4.z - bf2f(hh.z));
    hh.w = f2bf(o4.w); ll.w = f2bf(o4.w - bf2f(hh.w));
    ((ushort4*)(oh + (size_t)row * Cz))[threadIdx.x] = hh;
    ((ushort4*)(ol + (size_t)row * Cz))[threadIdx.x] = ll;
}

// ---------------- bf16-split tensor-core GEMM (pipelined) --------------------
#define ASTR 40
#define BSTR 136
#define A_T  (128 * ASTR)
#define B_T  (32 * BSTR)
#define STG  (2 * A_T + 2 * B_T)

__global__ __launch_bounds__(512)
void gemm_bs(const ushort_t* __restrict__ Ah, const ushort_t* __restrict__ Al,
             const ushort_t* __restrict__ Bh, const ushort_t* __restrict__ Bl,
             const float* __restrict__ bias, const float* __restrict__ Res,
             float* __restrict__ Cf, ushort_t* __restrict__ Ch,
             ushort_t* __restrict__ Cl, int M, int N, int K, int act) {
    extern __shared__ ushort_t smem[];

    const int tid = threadIdx.x;
    const int lane = tid & 31;
    const int wid = tid >> 5;
    const int wm = wid >> 2;
    const int wn = wid & 3;
    const int bm = blockIdx.y * 128, bn = blockIdx.x * 128;

    uint32_t sbase = (uint32_t)__cvta_generic_to_shared(smem);

    float acc[2][4][4];
    #pragma unroll
    for (int i = 0; i < 2; i++)
        #pragma unroll
        for (int j = 0; j < 4; j++)
            #pragma unroll
            for (int e = 0; e < 4; e++) acc[i][j][e] = 0.f;

    const int ar = tid >> 2, ac8 = (tid & 3) * 8;
    const int br = tid >> 4, bc8 = (tid & 15) * 8;
    const ushort_t* gAh = Ah + (size_t)(bm + ar) * K + ac8;
    const ushort_t* gAl = Al + (size_t)(bm + ar) * K + ac8;
    const ushort_t* gBh = Bh + (size_t)br * N + bn + bc8;
    const ushort_t* gBl = Bl + (size_t)br * N + bn + bc8;
    const uint32_t dA = sbase + (uint32_t)(ar * ASTR + ac8) * 2;
    const uint32_t dB = sbase + (uint32_t)(2 * A_T + br * BSTR + bc8) * 2;

    const int nk = K >> 5;

    auto issue = [&](int kt, int s) {
        uint32_t so = (uint32_t)(s * STG) * 2;
        CP16(dA + so,            gAh + kt * 32);
        CP16(dA + so + A_T * 2,  gAl + kt * 32);
        CP16(dB + so,            gBh + (size_t)kt * 32 * N);
        CP16(dB + so + B_T * 2,  gBl + (size_t)kt * 32 * N);
        CPCOMMIT();
    };

    issue(0, 0);

    const int a_r = lane & 15;
    const int a_c = (lane >> 4) * 8;

    for (int kt = 0; kt < nk; kt++) {
        if (kt + 1 < nk) { issue(kt + 1, (kt + 1) & 1); CPWAIT(1); }
        else             { CPWAIT(0); }
        __syncthreads();

        uint32_t s0 = sbase + (uint32_t)((kt & 1) * STG) * 2;
        #pragma unroll
        for (int ks = 0; ks < 2; ks++) {
            uint32_t ah[2][4], al[2][4], bh[4][2], bl[4][2];
            #pragma unroll
            for (int mt = 0; mt < 2; mt++) {
                uint32_t off = s0 + (uint32_t)(((wm * 32 + mt * 16 + a_r) * ASTR
                                               + ks * 16 + a_c) * 2);
                LDSM_X4(ah[mt][0], ah[mt][1], ah[mt][2], ah[mt][3], off);
                LDSM_X4(al[mt][0], al[mt][1], al[mt][2], al[mt][3], off + A_T * 2);
            }
            #pragma unroll
            for (int nt = 0; nt < 4; nt++) {
                uint32_t off = s0 + (uint32_t)((2 * A_T
                                                + (ks * 16 + a_r) * BSTR
                                                + wn * 32 + nt * 8) * 2);
                LDSM_X2T(bh[nt][0], bh[nt][1], off);
                LDSM_X2T(bl[nt][0], bl[nt][1], off + B_T * 2);
            }
            #pragma unroll
            for (int mt = 0; mt < 2; mt++)
                #pragma unroll
                for (int nt = 0; nt < 4; nt++) {
                    MMA16816(acc[mt][nt], ah[mt], bh[nt]);
                    MMA16816(acc[mt][nt], ah[mt], bl[nt]);
                    MMA16816(acc[mt][nt], al[mt], bh[nt]);
                }
        }
        __syncthreads();
    }

    int crow = lane >> 2;
    int ccol = (lane & 3) * 2;
    #pragma unroll
    for (int mt = 0; mt < 2; mt++) {
        #pragma unroll
        for (int nt = 0; nt < 4; nt++) {
            int col = bn + wn * 32 + nt * 8 + ccol;
            float b0 = bias[col], b1 = bias[col + 1];
            #pragma unroll
            for (int half = 0; half < 2; half++) {
                int row = bm + wm * 32 + mt * 16 + crow + half * 8;
                size_t off = (size_t)row * N + col;
                float c0 = acc[mt][nt][half * 2 + 0] + b0;
                float c1 = acc[mt][nt][half * 2 + 1] + b1;
                if (Res) {
                    float2 r = *(const float2*)(Res + off);
                    c0 += r.x; c1 += r.y;
                }
                if (act) { c0 = gelu_tanh(c0); c1 = gelu_tanh(c1); }
                if (Cf) *(float2*)(Cf + off) = make_float2(c0, c1);
                if (Ch) {
                    ushort_t h0 = f2bf(c0), h1 = f2bf(c1);
                    ushort2 hh; hh.x = h0; hh.y = h1;
                    ushort2 ll;
                    ll.x = f2bf(c0 - bf2f(h0));
                    ll.y = f2bf(c1 - bf2f(h1));
                    *(ushort2*)(Ch + off) = hh;
                    *(ushort2*)(Cl + off) = ll;
                }
            }
        }
    }
}

// ---------------- tensor-core flash attention --------------------------------
// Bq=64 (4 warps x 16 rows), Bk=64, D=64. Split-bf16 Q/K (3-term logits),
// bf16 P x split V (2-term). cp.async double-buffered K/V.
#define QSTR2 72
#define QT2   (64 * QSTR2)          // 4608 elems per plane
#define ATT_SMEM ((2 * QT2 + 2 * 4 * QT2) * 2)   // 92160 B

template <bool CAUSAL>
__global__ __launch_bounds__(128)
void attn_mma(const ushort_t* __restrict__ Qh, const ushort_t* __restrict__ Ql,
              int ldq,
              const ushort_t* __restrict__ Kh, const ushort_t* __restrict__ Kl,
              int ldk,
              const ushort_t* __restrict__ Vh, const ushort_t* __restrict__ Vl,
              int ldv,
              ushort_t* __restrict__ Oh, ushort_t* __restrict__ Ol, int S) {
    extern __shared__ ushort_t sm[];
    const int tid = threadIdx.x, lane = tid & 31, w = tid >> 5;
    const int bh = blockIdx.y, b = bh >> 4, h = bh & 15;
    const int qbase = blockIdx.x * 64;

    const ushort_t* qgh = Qh + (size_t)(b * Tz + qbase) * ldq + h * 64;
    const ushort_t* qgl = Ql + (size_t)(b * Tz + qbase) * ldq + h * 64;
    const ushort_t* kgh = Kh + (size_t)b * S * ldk + h * 64;
    const ushort_t* kgl = Kl + (size_t)b * S * ldk + h * 64;
    const ushort_t* vgh = Vh + (size_t)b * S * ldv + h * 64;
    const ushort_t* vgl = Vl + (size_t)b * S * ldv + h * 64;

    uint32_t sb = (uint32_t)__cvta_generic_to_shared(sm);
    const int nt = CAUSAL ? (blockIdx.x + 1) : (S / 64);

    // load row/col mapping for cp.async: 4 chunks of 16B per plane per thread
    const int cr = tid >> 1;                  // via id: row = id>>3
    auto issue_kv = [&](int t, int st) {
        uint32_t base = sb + (uint32_t)(2 * QT2 + st * 4 * QT2) * 2;
        const ushort_t* kh = kgh + (size_t)t * 64 * ldk;
        const ushort_t* kl = kgl + (size_t)t * 64 * ldk;
        const ushort_t* vh = vgh + (size_t)t * 64 * ldv;
        const ushort_t* vl = vgl + (size_t)t * 64 * ldv;
        #pragma unroll
        for (int i = 0; i < 4; i++) {
            int id = i * 128 + tid;
            int r = id >> 3, c8 = (id & 7) * 8;
            uint32_t off = (uint32_t)(r * QSTR2 + c8) * 2;
            CP16(base + off,                  kh + (size_t)r * ldk + c8);
            CP16(base + QT2 * 2 + off,        kl + (size_t)r * ldk + c8);
            CP16(base + 2 * QT2 * 2 + off,    vh + (size_t)r * ldv + c8);
            CP16(base + 3 * QT2 * 2 + off,    vl + (size_t)r * ldv + c8);
        }
        CPCOMMIT();
    };

    // Q into smem (same commit group as tile 0)
    #pragma unroll
    for (int i = 0; i < 4; i++) {
        int id = i * 128 + tid;
        int r = id >> 3, c8 = (id & 7) * 8;
        uint32_t off = (uint32_t)(r * QSTR2 + c8) * 2;
        CP16(sb + off,           qgh + (size_t)r * ldq + c8);
        CP16(sb + QT2 * 2 + off, qgl + (size_t)r * ldq + c8);
    }
    issue_kv(0, 0);

    uint32_t qh[4][4], ql[4][4];
    float o[8][4];
    #pragma unroll
    for (int n = 0; n < 8; n++)
        #pragma unroll
        for (int e = 0; e < 4; e++) o[n][e] = 0.f;
    float m0 = -1e30f, m1 = -1e30f, l0 = 0.f, l1 = 0.f;

    for (int t = 0; t < nt; t++) {
        if (t + 1 < nt) { issue_kv(t + 1, (t + 1) & 1); CPWAIT(1); }
        else            { CPWAIT(0); }
        __syncthreads();

        if (t == 0) {
            #pragma unroll
            for (int kk = 0; kk < 4; kk++) {
                uint32_t off = (uint32_t)(((w * 16 + (lane & 15)) * QSTR2
                                           + kk * 16 + (lane >> 4) * 8) * 2);
                LDSM_X4(qh[kk][0], qh[kk][1], qh[kk][2], qh[kk][3], sb + off);
                LDSM_X4(ql[kk][0], ql[kk][1], ql[kk][2], ql[kk][3],
                        sb + QT2 * 2 + off);
            }
        }

        uint32_t kvb = sb + (uint32_t)(2 * QT2 + (t & 1) * 4 * QT2) * 2;
        uint32_t kbH = kvb, kbL = kvb + QT2 * 2;
        uint32_t vbH = kvb + 2 * QT2 * 2, vbL = kvb + 3 * QT2 * 2;

        // --- S = Q K^T (3-term) ---
        float s[8][4];
        #pragma unroll
        for (int n = 0; n < 8; n++)
            #pragma unroll
            for (int e = 0; e < 4; e++) s[n][e] = 0.f;

        #pragma unroll
        for (int kk = 0; kk < 4; kk++) {
            #pragma unroll
            for (int np = 0; np < 4; np++) {
                uint32_t off = (uint32_t)(((np * 16 + ((lane >> 4) & 1) * 8
                                            + (lane & 7)) * QSTR2
                                           + kk * 16 + ((lane >> 3) & 1) * 8) * 2);
                uint32_t r0, r1, r2, r3, t0, t1, t2, t3;
                LDSM_X4(r0, r1, r2, r3, kbH + off);
                LDSM_X4(t0, t1, t2, t3, kbL + off);
                MMA2(s[2 * np],     qh[kk], r0, r1);
                MMA2(s[2 * np],     qh[kk], t0, t1);
                MMA2(s[2 * np],     ql[kk], r0, r1);
                MMA2(s[2 * np + 1], qh[kk], r2, r3);
                MMA2(s[2 * np + 1], qh[kk], t2, t3);
                MMA2(s[2 * np + 1], ql[kk], r2, r3);
            }
        }

        // --- softmax (online) ---
        const bool domask = CAUSAL && (t == nt - 1);
        const int rloc0 = w * 16 + (lane >> 2);
        float mx0 = -1e30f, mx1 = -1e30f;
        #pragma unroll
        for (int n = 0; n < 8; n++) {
            #pragma unroll
            for (int e = 0; e < 4; e++) {
                float v = s[n][e] * 0.125f;
                if (domask) {
                    int colL = n * 8 + (lane & 3) * 2 + (e & 1);
                    int rowL = rloc0 + ((e >= 2) ? 8 : 0);
                    if (colL > rowL) v = -1e30f;
                }
                s[n][e] = v;
                if (e < 2) mx0 = fmaxf(mx0, v); else mx1 = fmaxf(mx1, v);
            }
        }
        mx0 = fmaxf(mx0, __shfl_xor_sync(0xffffffffu, mx0, 1));
        mx0 = fmaxf(mx0, __shfl_xor_sync(0xffffffffu, mx0, 2));
        mx1 = fmaxf(mx1, __shfl_xor_sync(0xffffffffu, mx1, 1));
        mx1 = fmaxf(mx1, __shfl_xor_sync(0xffffffffu, mx1, 2));
        float mn0 = fmaxf(m0, mx0), mn1 = fmaxf(m1, mx1);
        float sc0 = ex2(1.44269504f * (m0 - mn0));
        float sc1 = ex2(1.44269504f * (m1 - mn1));
        l0 *= sc0; l1 *= sc1; m0 = mn0; m1 = mn1;
        #pragma unroll
        for (int n = 0; n < 8; n++) {
            o[n][0] *= sc0; o[n][1] *= sc0; o[n][2] *= sc1; o[n][3] *= sc1;
        }
        #pragma unroll
        for (int n = 0; n < 8; n++) {
            float p0 = ex2(1.44269504f * (s[n][0] - m0));
            float p1 = ex2(1.44269504f * (s[n][1] - m0));
            float p2 = ex2(1.44269504f * (s[n][2] - m1));
            float p3 = ex2(1.44269504f * (s[n][3] - m1));
            s[n][0] = p0; s[n][1] = p1; s[n][2] = p2; s[n][3] = p3;
            l0 += p0 + p1; l1 += p2 + p3;
        }

        // --- O += P V (2-term) ---
        #pragma unroll
        for (int kk2 = 0; kk2 < 4; kk2++) {
            uint32_t pa[4];
            pa[0] = packbf(s[2 * kk2][0],     s[2 * kk2][1]);
            pa[1] = packbf(s[2 * kk2][2],     s[2 * kk2][3]);
            pa[2] = packbf(s[2 * kk2 + 1][0], s[2 * kk2 + 1][1]);
            pa[3] = packbf(s[2 * kk2 + 1][2], s[2 * kk2 + 1][3]);
            #pragma unroll
            for (int np = 0; np < 4; np++) {
                uint32_t off = (uint32_t)(((kk2 * 16 + (lane & 15)) * QSTR2
                                           + np * 16 + (lane >> 4) * 8) * 2);
                uint32_t r0, r1, r2, r3, t0, t1, t2, t3;
                LDSM_X4T(r0, r1, r2, r3, vbH + off);
                LDSM_X4T(t0, t1, t2, t3, vbL + off);
                MMA2(o[2 * np],     pa, r0, r1);
                MMA2(o[2 * np],     pa, t0, t1);
                MMA2(o[2 * np + 1], pa, r2, r3);
                MMA2(o[2 * np + 1], pa, t2, t3);
            }
        }
        __syncthreads();
    }

    // finalize
    l0 += __shfl_xor_sync(0xffffffffu, l0, 1);
    l0 += __shfl_xor_sync(0xffffffffu, l0, 2);
    l1 += __shfl_xor_sync(0xffffffffu, l1, 1);
    l1 += __shfl_xor_sync(0xffffffffu, l1, 2);
    float inv0 = 1.f / l0, inv1 = 1.f / l1;

    size_t gr0 = (size_t)(b * Tz + qbase + w * 16 + (lane >> 2)) * Cz
                 + h * 64 + (lane & 3) * 2;
    #pragma unroll
    for (int n = 0; n < 8; n++) {
        size_t off0 = gr0 + n * 8;
        size_t off1 = off0 + 8 * Cz;
        float c0 = o[n][0] * inv0, c1 = o[n][1] * inv0;
        float c2 = o[n][2] * inv1, c3 = o[n][3] * inv1;
        ushort_t h0 = f2bf(c0), h1 = f2bf(c1), h2 = f2bf(c2), h3 = f2bf(c3);
        ushort2 hh0; hh0.x = h0; hh0.y = h1;
        ushort2 hh1; hh1.x = h2; hh1.y = h3;
        ushort2 ll0; ll0.x = f2bf(c0 - bf2f(h0)); ll0.y = f2bf(c1 - bf2f(h1));
        ushort2 ll1; ll1.x = f2bf(c2 - bf2f(h2)); ll1.y = f2bf(c3 - bf2f(h3));
        *(ushort2*)(Oh + off0) = hh0;
        *(ushort2*)(Ol + off0) = ll0;
        *(ushort2*)(Oh + off1) = hh1;
        *(ushort2*)(Ol + off1) = ll1;
    }
}

// ---------------- orchestration ----------------------------------------------
extern "C" void kernel_launch(void* const* d_in, const int* in_sizes, int n_in,
                              void* d_out, int out_size) {
    const float* x      = (const float*)d_in[0];
    const float* ximg   = (const float*)d_in[1];
    const float* ln1g   = (const float*)d_in[2];
    const float* ln1b   = (const float*)d_in[3];
    const float* ln2g   = (const float*)d_in[4];
    const float* ln2b   = (const float*)d_in[5];
    const float* Wattn  = (const float*)d_in[6];
    const float* battn  = (const float*)d_in[7];
    const float* Waproj = (const float*)d_in[8];
    const float* baproj = (const float*)d_in[9];
    const float* Wq     = (const float*)d_in[10];
    const float* bq     = (const float*)d_in[11];
    const float* Wk     = (const float*)d_in[12];
    const float* bk     = (const float*)d_in[13];
    const float* Wv     = (const float*)d_in[14];
    const float* bv     = (const float*)d_in[15];
    const float* Wcproj = (const float*)d_in[16];
    const float* bcproj = (const float*)d_in[17];
    const float* Wfc    = (const float*)d_in[18];
    const float* bfc    = (const float*)d_in[19];
    const float* Wmproj = (const float*)d_in[20];
    const float* bmproj = (const float*)d_in[21];
    float* out = (float*)d_out;

    ushort_t *wh, *wl, *hh, *hl, *ah, *al, *xih, *xil, *ffh, *ffl;
    ushort_t *qkvh, *qkvl, *q2h, *q2l, *k2h, *k2l, *v2h, *v2l;
    float *px;
    cudaGetSymbolAddress((void**)&wh,   g_wh);
    cudaGetSymbolAddress((void**)&wl,   g_wl);
    cudaGetSymbolAddress((void**)&hh,   g_hh);
    cudaGetSymbolAddress((void**)&hl,   g_hl);
    cudaGetSymbolAddress((void**)&ah,   g_ah);
    cudaGetSymbolAddress((void**)&al,   g_al);
    cudaGetSymbolAddress((void**)&xih,  g_xih);
    cudaGetSymbolAddress((void**)&xil,  g_xil);
    cudaGetSymbolAddress((void**)&ffh,  g_ffh);
    cudaGetSymbolAddress((void**)&ffl,  g_ffl);
    cudaGetSymbolAddress((void**)&qkvh, g_qkvh);
    cudaGetSymbolAddress((void**)&qkvl, g_qkvl);
    cudaGetSymbolAddress((void**)&q2h,  g_q2h);
    cudaGetSymbolAddress((void**)&q2l,  g_q2l);
    cudaGetSymbolAddress((void**)&k2h,  g_k2h);
    cudaGetSymbolAddress((void**)&k2l,  g_k2l);
    cudaGetSymbolAddress((void**)&v2h,  g_v2h);
    cudaGetSymbolAddress((void**)&v2l,  g_v2l);
    cudaGetSymbolAddress((void**)&px,   g_x);

    const int M  = Bz * Tz;
    const int Mi = Bz * TIz;
    const int SMEM = STG * 2 * 2;

    cudaFuncSetAttribute(gemm_bs, cudaFuncAttributeMaxDynamicSharedMemorySize,
                         SMEM);
    cudaFuncSetAttribute(attn_mma<true>,
                         cudaFuncAttributeMaxDynamicSharedMemorySize, ATT_SMEM);
    cudaFuncSetAttribute(attn_mma<false>,
                         cudaFuncAttributeMaxDynamicSharedMemorySize, ATT_SMEM);

    #define SPLIT(src, dh, dl, n) \
        split_kernel<<<(n) / 1024, 256>>>(src, dh, dl, (n) / 4)
    SPLIT(Wattn,  wh + OFF_WATTN,  wl + OFF_WATTN,  3 * Cz * Cz);
    SPLIT(Waproj, wh + OFF_WAPROJ, wl + OFF_WAPROJ, Cz * Cz);
    SPLIT(Wq,     wh + OFF_WQ,     wl + OFF_WQ,     Cz * Cz);
    SPLIT(Wk,     wh + OFF_WK,     wl + OFF_WK,     Cz * Cz);
    SPLIT(Wv,     wh + OFF_WV,     wl + OFF_WV,     Cz * Cz);
    SPLIT(Wcproj, wh + OFF_WCPROJ, wl + OFF_WCPROJ, Cz * Cz);
    SPLIT(Wfc,    wh + OFF_WFC,    wl + OFF_WFC,    Cz * FFz);
    SPLIT(Wmproj, wh + OFF_WMPROJ, wl + OFF_WMPROJ, FFz * Cz);
    SPLIT(ximg,   xih,             xil,             Mi * Cz);

    // --- causal self-attention ---
    ln_kernel<<<M, 256>>>(x, ln1g, ln1b, hh, hl);
    gemm_bs<<<dim3(3 * Cz / 128, M / 128), 512, SMEM>>>(
        hh, hl, wh + OFF_WATTN, wl + OFF_WATTN, battn, nullptr,
        nullptr, qkvh, qkvl, M, 3 * Cz, Cz, 0);
    attn_mma<true><<<dim3(Tz / 64, Bz * Hz), 128, ATT_SMEM>>>(
        qkvh, qkvl, 3 * Cz, qkvh + Cz, qkvl + Cz, 3 * Cz,
        qkvh + 2 * Cz, qkvl + 2 * Cz, 3 * Cz, ah, al, Tz);
    gemm_bs<<<dim3(Cz / 128, M / 128), 512, SMEM>>>(
        ah, al, wh + OFF_WAPROJ, wl + OFF_WAPROJ, baproj, x,
        px, nullptr, nullptr, M, Cz, Cz, 0);

    // --- cross-attention ---
    ln_kernel<<<M, 256>>>(px, ln1g, ln1b, hh, hl);
    gemm_bs<<<dim3(Cz / 128, M / 128), 512, SMEM>>>(
        hh, hl, wh + OFF_WQ, wl + OFF_WQ, bq, nullptr,
        nullptr, q2h, q2l, M, Cz, Cz, 0);
    gemm_bs<<<dim3(Cz / 128, Mi / 128), 512, SMEM>>>(
        xih, xil, wh + OFF_WK, wl + OFF_WK, bk, nullptr,
        nullptr, k2h, k2l, Mi, Cz, Cz, 0);
    gemm_bs<<<dim3(Cz / 128, Mi / 128), 512, SMEM>>>(
        xih, xil, wh + OFF_WV, wl + OFF_WV, bv, nullptr,
        nullptr, v2h, v2l, Mi, Cz, Cz, 0);
    attn_mma<false><<<dim3(Tz / 64, Bz * Hz), 128, ATT_SMEM>>>(
        q2h, q2l, Cz, k2h, k2l, Cz, v2h, v2l, Cz, ah, al, TIz);
    gemm_bs<<<dim3(Cz / 128, M / 128), 512, SMEM>>>(
        ah, al, wh + OFF_WCPROJ, wl + OFF_WCPROJ, bcproj, px,
        px, nullptr, nullptr, M, Cz, Cz, 0);

    // --- MLP ---
    ln_kernel<<<M, 256>>>(px, ln2g, ln2b, hh, hl);
    gemm_bs<<<dim3(FFz / 128, M / 128), 512, SMEM>>>(
        hh, hl, wh + OFF_WFC, wl + OFF_WFC, bfc, nullptr,
        nullptr, ffh, ffl, M, FFz, Cz, 1);
    gemm_bs<<<dim3(Cz / 128, M / 128), 512, SMEM>>>(
        ffh, ffl, wh + OFF_WMPROJ, wl + OFF_WMPROJ, bmproj, px,
        out, nullptr, nullptr, M, Cz, FFz, 0);
}

// round 6
// speedup vs baseline: 3.5275x; 1.0345x over previous
#include <cuda_runtime.h>
#include <cuda_bf16.h>
#include <stdint.h>
#include <math.h>

// Problem dims
#define Bz  8
#define Tz  1024
#define Cz  1024
#define Hz  16
#define Dz  64
#define TIz 256
#define FFz 4096

typedef unsigned short ushort_t;

// ---------------- scratch (device globals) -----------------------------------
#define OFF_WATTN  0
#define OFF_WAPROJ 3145728
#define OFF_WQ     4194304
#define OFF_WK     5242880
#define OFF_WV     6291456
#define OFF_WCPROJ 7340032
#define OFF_WFC    8388608
#define OFF_WMPROJ 12582912
#define W_TOTAL    16777216

__device__ ushort_t g_wh[W_TOTAL];
__device__ ushort_t g_wl[W_TOTAL];

__device__ ushort_t g_hh  [Bz * Tz * Cz];
__device__ ushort_t g_hl  [Bz * Tz * Cz];
__device__ ushort_t g_ah  [Bz * Tz * Cz];
__device__ ushort_t g_al  [Bz * Tz * Cz];
__device__ ushort_t g_xih [Bz * TIz * Cz];
__device__ ushort_t g_xil [Bz * TIz * Cz];
__device__ ushort_t g_ffh [Bz * Tz * FFz];
__device__ ushort_t g_ffl [Bz * Tz * FFz];

__device__ ushort_t g_qkvh[Bz * Tz * 3 * Cz];
__device__ ushort_t g_qkvl[Bz * Tz * 3 * Cz];
__device__ ushort_t g_q2h [Bz * Tz * Cz];
__device__ ushort_t g_q2l [Bz * Tz * Cz];
__device__ ushort_t g_k2h [Bz * TIz * Cz];
__device__ ushort_t g_k2l [Bz * TIz * Cz];
__device__ ushort_t g_v2h [Bz * TIz * Cz];
__device__ ushort_t g_v2l [Bz * TIz * Cz];

__device__ float g_x[Bz * Tz * Cz];

// ---------------- helpers ----------------------------------------------------
__device__ __forceinline__ ushort_t f2bf(float v) {
    __nv_bfloat16 b = __float2bfloat16_rn(v);
    return *reinterpret_cast<ushort_t*>(&b);
}
__device__ __forceinline__ float bf2f(ushort_t u) {
    return __uint_as_float(((unsigned)u) << 16);
}
__device__ __forceinline__ uint32_t packbf(float a, float b) {
    return (uint32_t)f2bf(a) | ((uint32_t)f2bf(b) << 16);
}
__device__ __forceinline__ float ex2(float v) {
    float r;
    asm("ex2.approx.ftz.f32 %0, %1;" : "=f"(r) : "f"(v));
    return r;
}
__device__ __forceinline__ float gelu_tanh(float v) {
    float u = 0.7978845608028654f * (v + 0.044715f * v * v * v);
    float t;
    asm("tanh.approx.f32 %0, %1;" : "=f"(t) : "f"(u));
    return 0.5f * v * (1.0f + t);
}

#define LDSM_X4(r0, r1, r2, r3, addr) \
    asm volatile("ldmatrix.sync.aligned.m8n8.x4.shared.b16 {%0,%1,%2,%3}, [%4];" \
                 : "=r"(r0), "=r"(r1), "=r"(r2), "=r"(r3) : "r"(addr))
#define LDSM_X4T(r0, r1, r2, r3, addr) \
    asm volatile("ldmatrix.sync.aligned.m8n8.x4.trans.shared.b16 {%0,%1,%2,%3}, [%4];" \
                 : "=r"(r0), "=r"(r1), "=r"(r2), "=r"(r3) : "r"(addr))
#define LDSM_X2T(r0, r1, addr) \
    asm volatile("ldmatrix.sync.aligned.m8n8.x2.trans.shared.b16 {%0,%1}, [%2];" \
                 : "=r"(r0), "=r"(r1) : "r"(addr))
#define MMA16816(c, a, b) \
    asm volatile("mma.sync.aligned.m16n8k16.row.col.f32.bf16.bf16.f32 " \
                 "{%0,%1,%2,%3}, {%4,%5,%6,%7}, {%8,%9}, {%0,%1,%2,%3};" \
                 : "+f"(c[0]), "+f"(c[1]), "+f"(c[2]), "+f"(c[3]) \
                 : "r"(a[0]), "r"(a[1]), "r"(a[2]), "r"(a[3]), "r"(b[0]), "r"(b[1]))
#define MMA2(c, a, b0_, b1_) \
    asm volatile("mma.sync.aligned.m16n8k16.row.col.f32.bf16.bf16.f32 " \
                 "{%0,%1,%2,%3}, {%4,%5,%6,%7}, {%8,%9}, {%0,%1,%2,%3};" \
                 : "+f"(c[0]), "+f"(c[1]), "+f"(c[2]), "+f"(c[3]) \
                 : "r"(a[0]), "r"(a[1]), "r"(a[2]), "r"(a[3]), "r"(b0_), "r"(b1_))
#define CP16(dst, src) \
    asm volatile("cp.async.cg.shared.global [%0], [%1], 16;" :: "r"(dst), "l"(src))
#define CPCOMMIT() asm volatile("cp.async.commit_group;")
#define CPWAIT(n)  asm volatile("cp.async.wait_group %0;" :: "n"(n))

// ---------------- split conversion (8 elems/thread) --------------------------
__global__ void split_kernel(const float* __restrict__ s,
                             ushort_t* __restrict__ h,
                             ushort_t* __restrict__ l, int n8) {
    int i = blockIdx.x * 256 + threadIdx.x;
    if (i < n8) {
        float4 v0 = ((const float4*)s)[2 * i];
        float4 v1 = ((const float4*)s)[2 * i + 1];
        ushort_t hh[8], ll[8];
        float v[8] = {v0.x, v0.y, v0.z, v0.w, v1.x, v1.y, v1.z, v1.w};
        #pragma unroll
        for (int j = 0; j < 8; j++) {
            hh[j] = f2bf(v[j]);
            ll[j] = f2bf(v[j] - bf2f(hh[j]));
        }
        uint4 ph, pl;
        ph.x = (uint32_t)hh[0] | ((uint32_t)hh[1] << 16);
        ph.y = (uint32_t)hh[2] | ((uint32_t)hh[3] << 16);
        ph.z = (uint32_t)hh[4] | ((uint32_t)hh[5] << 16);
        ph.w = (uint32_t)hh[6] | ((uint32_t)hh[7] << 16);
        pl.x = (uint32_t)ll[0] | ((uint32_t)ll[1] << 16);
        pl.y = (uint32_t)ll[2] | ((uint32_t)ll[3] << 16);
        pl.z = (uint32_t)ll[4] | ((uint32_t)ll[5] << 16);
        pl.w = (uint32_t)ll[6] | ((uint32_t)ll[7] << 16);
        ((uint4*)h)[i] = ph;
        ((uint4*)l)[i] = pl;
    }
}

// ---------------- LayerNorm -> split -----------------------------------------
__global__ void ln_kernel(const float* __restrict__ x,
                          const float* __restrict__ gam,
                          const float* __restrict__ bet,
                          ushort_t* __restrict__ oh,
                          ushort_t* __restrict__ ol) {
    int row = blockIdx.x;
    const float4* xp = (const float4*)(x + (size_t)row * Cz);
    float4 v = xp[threadIdx.x];
    float s  = v.x + v.y + v.z + v.w;
    float sq = v.x * v.x + v.y * v.y + v.z * v.z + v.w * v.w;

    __shared__ float rs[8], rq[8];
    #pragma unroll
    for (int o = 16; o > 0; o >>= 1) {
        s  += __shfl_down_sync(0xffffffffu, s,  o);
        sq += __shfl_down_sync(0xffffffffu, sq, o);
    }
    int wid = threadIdx.x >> 5, lid = threadIdx.x & 31;
    if (lid == 0) { rs[wid] = s; rq[wid] = sq; }
    __syncthreads();
    if (wid == 0) {
        s  = (lid < 8) ? rs[lid] : 0.f;
        sq = (lid < 8) ? rq[lid] : 0.f;
        #pragma unroll
        for (int o = 4; o > 0; o >>= 1) {
            s  += __shfl_down_sync(0xffffffffu, s,  o);
            sq += __shfl_down_sync(0xffffffffu, sq, o);
        }
        if (lid == 0) { rs[0] = s; rq[0] = sq; }
    }
    __syncthreads();
    float mu  = rs[0] * (1.0f / Cz);
    float var = rq[0] * (1.0f / Cz) - mu * mu;
    float inv = rsqrtf(var + 1e-5f);

    float4 gv = ((const float4*)gam)[threadIdx.x];
    float4 bv = ((const float4*)bet)[threadIdx.x];
    float4 o4;
    o4.x = (v.x - mu) * inv * gv.x + bv.x;
    o4.y = (v.y - mu) * inv * gv.y + bv.y;
    o4.z = (v.z - mu) * inv * gv.z + bv.z;
    o4.w = (v.w - mu) * inv * gv.w + bv.w;
    ushort4 hh, ll;
    hh.x = f2bf(o4.x); ll.x = f2bf(o4.x - bf2f(hh.x));
    hh.y = f2bf(o4.y); ll.y = f2bf(o4.y - bf2f(hh.y));
    hh.z = f2bf(o4.z); ll.z = f2bf(o4.z - bf2f(hh.z));
    hh.w = f2bf(o4.w); ll.w = f2bf(o4.w - bf2f(hh.w));
    ((ushort4*)(oh + (size_t)row * Cz))[threadIdx.x] = hh;
    ((ushort4*)(ol + (size_t)row * Cz))[threadIdx.x] = ll;
}

// ---------------- bf16-split tensor-core GEMM (256x128x32, 3-stage) ----------
#define ASTR 40
#define BSTR 136
#define A_T  (256 * ASTR)              // 10240 elems per A plane
#define B_T  (32 * BSTR)               // 4352  elems per B plane
#define STG  (2 * A_T + 2 * B_T)       // 29184 elems per stage
#define NSTAGE 3
#define GEMM_SMEM (STG * NSTAGE * 2)   // bytes

__global__ __launch_bounds__(512)
void gemm_bs(const ushort_t* __restrict__ Ah, const ushort_t* __restrict__ Al,
             const ushort_t* __restrict__ Bh, const ushort_t* __restrict__ Bl,
             const float* __restrict__ bias, const float* __restrict__ Res,
             float* __restrict__ Cf, ushort_t* __restrict__ Ch,
             ushort_t* __restrict__ Cl, int M, int N, int K, int act) {
    extern __shared__ ushort_t smem[];

    const int tid = threadIdx.x;
    const int lane = tid & 31;
    const int wid = tid >> 5;
    const int wm = wid >> 2;          // 0..3, 64 rows each
    const int wn = wid & 3;           // 0..3, 32 cols each
    const int bm = blockIdx.y * 256, bn = blockIdx.x * 128;

    uint32_t sbase = (uint32_t)__cvta_generic_to_shared(smem);

    float acc[4][4][4];
    #pragma unroll
    for (int i = 0; i < 4; i++)
        #pragma unroll
        for (int j = 0; j < 4; j++)
            #pragma unroll
            for (int e = 0; e < 4; e++) acc[i][j][e] = 0.f;

    // cp.async mapping: A 2 chunks/plane/thread, B 1 chunk/plane/thread
    const int ar0 = tid >> 2,        ac0 = (tid & 3) * 8;
    const int ar1 = (512 + tid) >> 2, ac1 = ((512 + tid) & 3) * 8;
    const int bk = tid >> 4, bc8 = (tid & 15) * 8;
    const ushort_t* gAh = Ah + (size_t)bm * K;
    const ushort_t* gAl = Al + (size_t)bm * K;
    const ushort_t* gBh = Bh + (size_t)bk * N + bn + bc8;
    const ushort_t* gBl = Bl + (size_t)bk * N + bn + bc8;

    const int nk = K >> 5;

    auto issue = [&](int kt) {
        uint32_t so = sbase + (uint32_t)((kt % NSTAGE) * STG) * 2;
        const ushort_t* ah0 = gAh + (size_t)ar0 * K + kt * 32 + ac0;
        const ushort_t* ah1 = gAh + (size_t)ar1 * K + kt * 32 + ac1;
        const ushort_t* al0 = gAl + (size_t)ar0 * K + kt * 32 + ac0;
        const ushort_t* al1 = gAl + (size_t)ar1 * K + kt * 32 + ac1;
        CP16(so + (uint32_t)(ar0 * ASTR + ac0) * 2,           ah0);
        CP16(so + (uint32_t)(ar1 * ASTR + ac1) * 2,           ah1);
        CP16(so + (uint32_t)(A_T + ar0 * ASTR + ac0) * 2,     al0);
        CP16(so + (uint32_t)(A_T + ar1 * ASTR + ac1) * 2,     al1);
        CP16(so + (uint32_t)(2 * A_T + bk * BSTR + bc8) * 2,  gBh + (size_t)kt * 32 * N);
        CP16(so + (uint32_t)(2 * A_T + B_T + bk * BSTR + bc8) * 2,
             gBl + (size_t)kt * 32 * N);
        CPCOMMIT();
    };

    issue(0);
    if (nk > 1) issue(1);

    const int a_r = lane & 15;
    const int a_c = (lane >> 4) * 8;

    for (int kt = 0; kt < nk; kt++) {
        if (kt + 2 < nk) issue(kt + 2);
        int rem = nk - 1 - kt;
        if (rem >= 2)      { CPWAIT(2); }
        else if (rem == 1) { CPWAIT(1); }
        else               { CPWAIT(0); }
        __syncthreads();

        uint32_t s0 = sbase + (uint32_t)((kt % NSTAGE) * STG) * 2;
        #pragma unroll
        for (int ks = 0; ks < 2; ks++) {
            uint32_t bh[4][2], bl[4][2];
            #pragma unroll
            for (int nt = 0; nt < 4; nt++) {
                uint32_t off = s0 + (uint32_t)((2 * A_T
                                                + (ks * 16 + a_r) * BSTR
                                                + wn * 32 + nt * 8) * 2);
                LDSM_X2T(bh[nt][0], bh[nt][1], off);
                LDSM_X2T(bl[nt][0], bl[nt][1], off + B_T * 2);
            }
            #pragma unroll
            for (int mt = 0; mt < 4; mt++) {
                uint32_t ah[4], al[4];
                uint32_t off = s0 + (uint32_t)(((wm * 64 + mt * 16 + a_r) * ASTR
                                               + ks * 16 + a_c) * 2);
                LDSM_X4(ah[0], ah[1], ah[2], ah[3], off);
                LDSM_X4(al[0], al[1], al[2], al[3], off + A_T * 2);
                #pragma unroll
                for (int nt = 0; nt < 4; nt++) {
                    MMA16816(acc[mt][nt], ah, bh[nt]);
                    MMA16816(acc[mt][nt], ah, bl[nt]);
                    MMA16816(acc[mt][nt], al, bh[nt]);
                }
            }
        }
        __syncthreads();
    }

    int crow = lane >> 2;
    int ccol = (lane & 3) * 2;
    #pragma unroll
    for (int mt = 0; mt < 4; mt++) {
        #pragma unroll
        for (int nt = 0; nt < 4; nt++) {
            int col = bn + wn * 32 + nt * 8 + ccol;
            float b0 = bias[col], b1 = bias[col + 1];
            #pragma unroll
            for (int half = 0; half < 2; half++) {
                int row = bm + wm * 64 + mt * 16 + crow + half * 8;
                size_t off = (size_t)row * N + col;
                float c0 = acc[mt][nt][half * 2 + 0] + b0;
                float c1 = acc[mt][nt][half * 2 + 1] + b1;
                if (Res) {
                    float2 r = *(const float2*)(Res + off);
                    c0 += r.x; c1 += r.y;
                }
                if (act) { c0 = gelu_tanh(c0); c1 = gelu_tanh(c1); }
                if (Cf) *(float2*)(Cf + off) = make_float2(c0, c1);
                if (Ch) {
                    ushort_t h0 = f2bf(c0), h1 = f2bf(c1);
                    ushort2 hh; hh.x = h0; hh.y = h1;
                    ushort2 ll;
                    ll.x = f2bf(c0 - bf2f(h0));
                    ll.y = f2bf(c1 - bf2f(h1));
                    *(ushort2*)(Ch + off) = hh;
                    *(ushort2*)(Cl + off) = ll;
                }
            }
        }
    }
}

// ---------------- tensor-core flash attention --------------------------------
// Bq=128 (8 warps x 16 rows), Bk=64, D=64, 256 threads.
// S = QK^T 3-term split; P bf16 x Vh (single plane). 2-stage cp.async.
#define QSTR 72
#define QT   (128 * QSTR)               // Q plane elems
#define KT   (64 * QSTR)                // KV plane elems
#define ATT_SMEM ((2 * QT + 2 * 3 * KT) * 2)   // 92160 B

template <bool CAUSAL>
__global__ __launch_bounds__(256)
void attn_mma(const ushort_t* __restrict__ Qh, const ushort_t* __restrict__ Ql,
              int ldq,
              const ushort_t* __restrict__ Kh, const ushort_t* __restrict__ Kl,
              int ldk,
              const ushort_t* __restrict__ Vh, int ldv,
              ushort_t* __restrict__ Oh, ushort_t* __restrict__ Ol, int S) {
    extern __shared__ ushort_t sm[];
    const int tid = threadIdx.x, lane = tid & 31, w = tid >> 5;
    const int bh = blockIdx.y, b = bh >> 4, h = bh & 15;
    const int qbase = blockIdx.x * 128;

    const ushort_t* qgh = Qh + (size_t)(b * Tz + qbase) * ldq + h * 64;
    const ushort_t* qgl = Ql + (size_t)(b * Tz + qbase) * ldq + h * 64;
    const ushort_t* kgh = Kh + (size_t)b * S * ldk + h * 64;
    const ushort_t* kgl = Kl + (size_t)b * S * ldk + h * 64;
    const ushort_t* vgh = Vh + (size_t)b * S * ldv + h * 64;

    uint32_t sb = (uint32_t)__cvta_generic_to_shared(sm);
    const int nt = CAUSAL ? 2 * (blockIdx.x + 1) : (S / 64);

    auto issue_kv = [&](int t, int st) {
        uint32_t base = sb + (uint32_t)(2 * QT + st * 3 * KT) * 2;
        const ushort_t* kh = kgh + (size_t)t * 64 * ldk;
        const ushort_t* kl = kgl + (size_t)t * 64 * ldk;
        const ushort_t* vh = vgh + (size_t)t * 64 * ldv;
        #pragma unroll
        for (int i = 0; i < 2; i++) {
            int id = i * 256 + tid;
            int r = id >> 3, c8 = (id & 7) * 8;
            uint32_t off = (uint32_t)(r * QSTR + c8) * 2;
            CP16(base + off,              kh + (size_t)r * ldk + c8);
            CP16(base + KT * 2 + off,     kl + (size_t)r * ldk + c8);
            CP16(base + 2 * KT * 2 + off, vh + (size_t)r * ldv + c8);
        }
        CPCOMMIT();
    };

    // Q into smem (group 0, with KV tile 0)
    #pragma unroll
    for (int i = 0; i < 4; i++) {
        int id = i * 256 + tid;
        int r = id >> 3, c8 = (id & 7) * 8;
        uint32_t off = (uint32_t)(r * QSTR + c8) * 2;
        CP16(sb + off,          qgh + (size_t)r * ldq + c8);
        CP16(sb + QT * 2 + off, qgl + (size_t)r * ldq + c8);
    }
    issue_kv(0, 0);

    uint32_t qh[4][4], ql[4][4];
    float o[8][4];
    #pragma unroll
    for (int n = 0; n < 8; n++)
        #pragma unroll
        for (int e = 0; e < 4; e++) o[n][e] = 0.f;
    float m0 = -1e30f, m1 = -1e30f, l0 = 0.f, l1 = 0.f;

    for (int t = 0; t < nt; t++) {
        if (t + 1 < nt) { issue_kv(t + 1, (t + 1) & 1); CPWAIT(1); }
        else            { CPWAIT(0); }
        __syncthreads();

        if (t == 0) {
            #pragma unroll
            for (int kk = 0; kk < 4; kk++) {
                uint32_t off = (uint32_t)(((w * 16 + (lane & 15)) * QSTR
                                           + kk * 16 + (lane >> 4) * 8) * 2);
                LDSM_X4(qh[kk][0], qh[kk][1], qh[kk][2], qh[kk][3], sb + off);
                LDSM_X4(ql[kk][0], ql[kk][1], ql[kk][2], ql[kk][3],
                        sb + QT * 2 + off);
            }
        }

        uint32_t kvb = sb + (uint32_t)(2 * QT + (t & 1) * 3 * KT) * 2;
        uint32_t kbH = kvb, kbL = kvb + KT * 2;
        uint32_t vbH = kvb + 2 * KT * 2;

        // --- S = Q K^T (3-term) ---
        float s[8][4];
        #pragma unroll
        for (int n = 0; n < 8; n++)
            #pragma unroll
            for (int e = 0; e < 4; e++) s[n][e] = 0.f;

        #pragma unroll
        for (int kk = 0; kk < 4; kk++) {
            #pragma unroll
            for (int np = 0; np < 4; np++) {
                uint32_t off = (uint32_t)(((np * 16 + ((lane >> 4) & 1) * 8
                                            + (lane & 7)) * QSTR
                                           + kk * 16 + ((lane >> 3) & 1) * 8) * 2);
                uint32_t r0, r1, r2, r3, t0, t1, t2, t3;
                LDSM_X4(r0, r1, r2, r3, kbH + off);
                LDSM_X4(t0, t1, t2, t3, kbL + off);
                MMA2(s[2 * np],     qh[kk], r0, r1);
                MMA2(s[2 * np],     qh[kk], t0, t1);
                MMA2(s[2 * np],     ql[kk], r0, r1);
                MMA2(s[2 * np + 1], qh[kk], r2, r3);
                MMA2(s[2 * np + 1], qh[kk], t2, t3);
                MMA2(s[2 * np + 1], ql[kk], r2, r3);
            }
        }

        // --- softmax (online) ---
        const bool domask = CAUSAL && (t >= nt - 2);
        const int grow = qbase + w * 16 + (lane >> 2);
        float mx0 = -1e30f, mx1 = -1e30f;
        #pragma unroll
        for (int n = 0; n < 8; n++) {
            #pragma unroll
            for (int e = 0; e < 4; e++) {
                float v = s[n][e] * 0.125f;
                if (domask) {
                    int gcol = t * 64 + n * 8 + (lane & 3) * 2 + (e & 1);
                    int grw = grow + ((e >= 2) ? 8 : 0);
                    if (gcol > grw) v = -1e30f;
                }
                s[n][e] = v;
                if (e < 2) mx0 = fmaxf(mx0, v); else mx1 = fmaxf(mx1, v);
            }
        }
        mx0 = fmaxf(mx0, __shfl_xor_sync(0xffffffffu, mx0, 1));
        mx0 = fmaxf(mx0, __shfl_xor_sync(0xffffffffu, mx0, 2));
        mx1 = fmaxf(mx1, __shfl_xor_sync(0xffffffffu, mx1, 1));
        mx1 = fmaxf(mx1, __shfl_xor_sync(0xffffffffu, mx1, 2));
        float mn0 = fmaxf(m0, mx0), mn1 = fmaxf(m1, mx1);
        float sc0 = ex2(1.44269504f * (m0 - mn0));
        float sc1 = ex2(1.44269504f * (m1 - mn1));
        l0 *= sc0; l1 *= sc1; m0 = mn0; m1 = mn1;
        #pragma unroll
        for (int n = 0; n < 8; n++) {
            o[n][0] *= sc0; o[n][1] *= sc0; o[n][2] *= sc1; o[n][3] *= sc1;
        }
        #pragma unroll
        for (int n = 0; n < 8; n++) {
            float p0 = ex2(1.44269504f * (s[n][0] - m0));
            float p1 = ex2(1.44269504f * (s[n][1] - m0));
            float p2 = ex2(1.44269504f * (s[n][2] - m1));
            float p3 = ex2(1.44269504f * (s[n][3] - m1));
            s[n][0] = p0; s[n][1] = p1; s[n][2] = p2; s[n][3] = p3;
            l0 += p0 + p1; l1 += p2 + p3;
        }

        // --- O += P Vh ---
        #pragma unroll
        for (int kk2 = 0; kk2 < 4; kk2++) {
            uint32_t pa[4];
            pa[0] = packbf(s[2 * kk2][0],     s[2 * kk2][1]);
            pa[1] = packbf(s[2 * kk2][2],     s[2 * kk2][3]);
            pa[2] = packbf(s[2 * kk2 + 1][0], s[2 * kk2 + 1][1]);
            pa[3] = packbf(s[2 * kk2 + 1][2], s[2 * kk2 + 1][3]);
            #pragma unroll
            for (int np = 0; np < 4; np++) {
                uint32_t off = (uint32_t)(((kk2 * 16 + (lane & 15)) * QSTR
                                           + np * 16 + (lane >> 4) * 8) * 2);
                uint32_t r0, r1, r2, r3;
                LDSM_X4T(r0, r1, r2, r3, vbH + off);
                MMA2(o[2 * np],     pa, r0, r1);
                MMA2(o[2 * np + 1], pa, r2, r3);
            }
        }
        __syncthreads();
    }

    // finalize
    l0 += __shfl_xor_sync(0xffffffffu, l0, 1);
    l0 += __shfl_xor_sync(0xffffffffu, l0, 2);
    l1 += __shfl_xor_sync(0xffffffffu, l1, 1);
    l1 += __shfl_xor_sync(0xffffffffu, l1, 2);
    float inv0 = 1.f / l0, inv1 = 1.f / l1;

    size_t gr0 = (size_t)(b * Tz + qbase + w * 16 + (lane >> 2)) * Cz
                 + h * 64 + (lane & 3) * 2;
    #pragma unroll
    for (int n = 0; n < 8; n++) {
        size_t off0 = gr0 + n * 8;
        size_t off1 = off0 + 8 * Cz;
        float c0 = o[n][0] * inv0, c1 = o[n][1] * inv0;
        float c2 = o[n][2] * inv1, c3 = o[n][3] * inv1;
        ushort_t h0 = f2bf(c0), h1 = f2bf(c1), h2 = f2bf(c2), h3 = f2bf(c3);
        ushort2 hh0; hh0.x = h0; hh0.y = h1;
        ushort2 hh1; hh1.x = h2; hh1.y = h3;
        ushort2 ll0; ll0.x = f2bf(c0 - bf2f(h0)); ll0.y = f2bf(c1 - bf2f(h1));
        ushort2 ll1; ll1.x = f2bf(c2 - bf2f(h2)); ll1.y = f2bf(c3 - bf2f(h3));
        *(ushort2*)(Oh + off0) = hh0;
        *(ushort2*)(Ol + off0) = ll0;
        *(ushort2*)(Oh + off1) = hh1;
        *(ushort2*)(Ol + off1) = ll1;
    }
}

// ---------------- orchestration ----------------------------------------------
extern "C" void kernel_launch(void* const* d_in, const int* in_sizes, int n_in,
                              void* d_out, int out_size) {
    const float* x      = (const float*)d_in[0];
    const float* ximg   = (const float*)d_in[1];
    const float* ln1g   = (const float*)d_in[2];
    const float* ln1b   = (const float*)d_in[3];
    const float* ln2g   = (const float*)d_in[4];
    const float* ln2b   = (const float*)d_in[5];
    const float* Wattn  = (const float*)d_in[6];
    const float* battn  = (const float*)d_in[7];
    const float* Waproj = (const float*)d_in[8];
    const float* baproj = (const float*)d_in[9];
    const float* Wq     = (const float*)d_in[10];
    const float* bq     = (const float*)d_in[11];
    const float* Wk     = (const float*)d_in[12];
    const float* bk     = (const float*)d_in[13];
    const float* Wv     = (const float*)d_in[14];
    const float* bv     = (const float*)d_in[15];
    const float* Wcproj = (const float*)d_in[16];
    const float* bcproj = (const float*)d_in[17];
    const float* Wfc    = (const float*)d_in[18];
    const float* bfc    = (const float*)d_in[19];
    const float* Wmproj = (const float*)d_in[20];
    const float* bmproj = (const float*)d_in[21];
    float* out = (float*)d_out;

    ushort_t *wh, *wl, *hh, *hl, *ah, *al, *xih, *xil, *ffh, *ffl;
    ushort_t *qkvh, *qkvl, *q2h, *q2l, *k2h, *k2l, *v2h, *v2l;
    float *px;
    cudaGetSymbolAddress((void**)&wh,   g_wh);
    cudaGetSymbolAddress((void**)&wl,   g_wl);
    cudaGetSymbolAddress((void**)&hh,   g_hh);
    cudaGetSymbolAddress((void**)&hl,   g_hl);
    cudaGetSymbolAddress((void**)&ah,   g_ah);
    cudaGetSymbolAddress((void**)&al,   g_al);
    cudaGetSymbolAddress((void**)&xih,  g_xih);
    cudaGetSymbolAddress((void**)&xil,  g_xil);
    cudaGetSymbolAddress((void**)&ffh,  g_ffh);
    cudaGetSymbolAddress((void**)&ffl,  g_ffl);
    cudaGetSymbolAddress((void**)&qkvh, g_qkvh);
    cudaGetSymbolAddress((void**)&qkvl, g_qkvl);
    cudaGetSymbolAddress((void**)&q2h,  g_q2h);
    cudaGetSymbolAddress((void**)&q2l,  g_q2l);
    cudaGetSymbolAddress((void**)&k2h,  g_k2h);
    cudaGetSymbolAddress((void**)&k2l,  g_k2l);
    cudaGetSymbolAddress((void**)&v2h,  g_v2h);
    cudaGetSymbolAddress((void**)&v2l,  g_v2l);
    cudaGetSymbolAddress((void**)&px,   g_x);

    const int M  = Bz * Tz;
    const int Mi = Bz * TIz;

    cudaFuncSetAttribute(gemm_bs, cudaFuncAttributeMaxDynamicSharedMemorySize,
                         GEMM_SMEM);
    cudaFuncSetAttribute(attn_mma<true>,
                         cudaFuncAttributeMaxDynamicSharedMemorySize, ATT_SMEM);
    cudaFuncSetAttribute(attn_mma<false>,
                         cudaFuncAttributeMaxDynamicSharedMemorySize, ATT_SMEM);

    #define SPLIT(src, dh, dl, n) \
        split_kernel<<<(n) / 2048, 256>>>(src, dh, dl, (n) / 8)
    SPLIT(Wattn,  wh + OFF_WATTN,  wl + OFF_WATTN,  3 * Cz * Cz);
    SPLIT(Waproj, wh + OFF_WAPROJ, wl + OFF_WAPROJ, Cz * Cz);
    SPLIT(Wq,     wh + OFF_WQ,     wl + OFF_WQ,     Cz * Cz);
    SPLIT(Wk,     wh + OFF_WK,     wl + OFF_WK,     Cz * Cz);
    SPLIT(Wv,     wh + OFF_WV,     wl + OFF_WV,     Cz * Cz);
    SPLIT(Wcproj, wh + OFF_WCPROJ, wl + OFF_WCPROJ, Cz * Cz);
    SPLIT(Wfc,    wh + OFF_WFC,    wl + OFF_WFC,    Cz * FFz);
    SPLIT(Wmproj, wh + OFF_WMPROJ, wl + OFF_WMPROJ, FFz * Cz);
    SPLIT(ximg,   xih,             xil,             Mi * Cz);

    // --- causal self-attention ---
    ln_kernel<<<M, 256>>>(x, ln1g, ln1b, hh, hl);
    gemm_bs<<<dim3(3 * Cz / 128, M / 256), 512, GEMM_SMEM>>>(
        hh, hl, wh + OFF_WATTN, wl + OFF_WATTN, battn, nullptr,
        nullptr, qkvh, qkvl, M, 3 * Cz, Cz, 0);
    attn_mma<true><<<dim3(Tz / 128, Bz * Hz), 256, ATT_SMEM>>>(
        qkvh, qkvl, 3 * Cz, qkvh + Cz, qkvl + Cz, 3 * Cz,
        qkvh + 2 * Cz, 3 * Cz, ah, al, Tz);
    gemm_bs<<<dim3(Cz / 128, M / 256), 512, GEMM_SMEM>>>(
        ah, al, wh + OFF_WAPROJ, wl + OFF_WAPROJ, baproj, x,
        px, nullptr, nullptr, M, Cz, Cz, 0);

    // --- cross-attention ---
    ln_kernel<<<M, 256>>>(px, ln1g, ln1b, hh, hl);
    gemm_bs<<<dim3(Cz / 128, M / 256), 512, GEMM_SMEM>>>(
        hh, hl, wh + OFF_WQ, wl + OFF_WQ, bq, nullptr,
        nullptr, q2h, q2l, M, Cz, Cz, 0);
    gemm_bs<<<dim3(Cz / 128, Mi / 256), 512, GEMM_SMEM>>>(
        xih, xil, wh + OFF_WK, wl + OFF_WK, bk, nullptr,
        nullptr, k2h, k2l, Mi, Cz, Cz, 0);
    gemm_bs<<<dim3(Cz / 128, Mi / 256), 512, GEMM_SMEM>>>(
        xih, xil, wh + OFF_WV, wl + OFF_WV, bv, nullptr,
        nullptr, v2h, v2l, Mi, Cz, Cz, 0);
    attn_mma<false><<<dim3(Tz / 128, Bz * Hz), 256, ATT_SMEM>>>(
        q2h, q2l, Cz, k2h, k2l, Cz, v2h, Cz, ah, al, TIz);
    gemm_bs<<<dim3(Cz / 128, M / 256), 512, GEMM_SMEM>>>(
        ah, al, wh + OFF_WCPROJ, wl + OFF_WCPROJ, bcproj, px,
        px, nullptr, nullptr, M, Cz, Cz, 0);

    // --- MLP ---
    ln_kernel<<<M, 256>>>(px, ln2g, ln2b, hh, hl);
    gemm_bs<<<dim3(FFz / 128, M / 256), 512, GEMM_SMEM>>>(
        hh, hl, wh + OFF_WFC, wl + OFF_WFC, bfc, nullptr,
        nullptr, ffh, ffl, M, FFz, Cz, 1);
    gemm_bs<<<dim3(Cz / 128, M / 256), 512, GEMM_SMEM>>>(
        ffh, ffl, wh + OFF_WMPROJ, wl + OFF_WMPROJ, bmproj, px,
        out, nullptr, nullptr, M, Cz, FFz, 0);
}